// round 9
// baseline (speedup 1.0000x reference)
#include <cuda_runtime.h>
#include <mma.h>
#include <math.h>

using namespace nvcuda;

#define B_   2
#define S_   2048
#define D_   1024
#define H_   16
#define DC_  64
#define HC_  16
#define MFF_ 4096
#define DH_  64
#define BS_  (B_*S_)      // 4096
#define BH_  (B_*H_)      // 32

// ---------------- scratch (static device globals; no allocation) ----------------
__device__ float g_hn  [BS_*D_];
__device__ float g_val [BS_*D_];
__device__ float g_zh  [BS_*H_*HC_];
__device__ float g_attn[BS_*D_];
__device__ float g_h1  [BS_*D_];
__device__ float g_hn2 [BS_*D_];
__device__ float g_mid [BS_*MFF_];
__device__ float g_ztmp[BS_*DC_];

__device__ __forceinline__ float to_tf32(float x) {
    float r; asm("cvt.rna.tf32.f32 %0, %1;" : "=f"(r) : "f"(x)); return r;
}

// exp(s) for s <= 0, FMA-pipe only (no MUFU). ~2.4e-6 max rel err.
__device__ __forceinline__ float fast_exp_neg(float s) {
    float y = fmaxf(s * 1.4426950408889634f, -126.0f);   // log2(e)*s, clamped
    float z = y + 12582912.0f;                           // round-to-nearest int (1.5*2^23)
    float r = z - 12582912.0f;
    float f = y - r;                                     // f in [-0.5, 0.5]
    int   iz = __float_as_int(z);
    float sc = __int_as_float((iz + (127 - 0x400000)) << 23);   // 2^round(y)
    float p = 0.0013333558f;
    p = fmaf(p, f, 0.0096181291f);
    p = fmaf(p, f, 0.0555041087f);
    p = fmaf(p, f, 0.2402265070f);
    p = fmaf(p, f, 0.6931471806f);
    p = fmaf(p, f, 1.0f);
    return sc * p;
}

enum { EPI_BIAS = 0, EPI_RES = 1, EPI_GELU = 2 };

__device__ __forceinline__ void cp_async16(float* smem_dst, const float* gmem_src) {
    unsigned sa = (unsigned)__cvta_generic_to_shared(smem_dst);
    asm volatile("cp.async.cg.shared.global [%0], [%1], 16;\n" :: "r"(sa), "l"(gmem_src));
}
__device__ __forceinline__ void cp_commit() {
    asm volatile("cp.async.commit_group;\n" ::);
}

// ---------------- pipelined tf32 GEMM: C = epi(A[M,K] @ B[K,N] + bias) ----------------
template<int BM, int BN, int EPI>
__global__ void __launch_bounds__(256, 2) gemm_pipe(
    const float* __restrict__ A, const float* __restrict__ Bw,
    const float* __restrict__ bias, const float* __restrict__ Rres,
    float* __restrict__ C, int Mdim, int Ndim, int Kdim)
{
    constexpr int BK = 32;
    constexpr int STAGES = 3;
    constexpr int LDA = BK + 4;
    constexpr int LDB = BN + 4;
    constexpr int WGN = BN / 64;
    constexpr int WGM = 8 / WGN;
    constexpr int WTM = BM / WGM;
    constexpr int FM  = WTM / 16;
    constexpr int A_STG = BM * LDA;
    constexpr int B_STG = BK * LDB;

    extern __shared__ float sm[];
    float* As = sm;
    float* Bs = sm + STAGES * A_STG;

    const int tid = threadIdx.x;
    const int wid = tid >> 5;
    const int wm = wid / WGN, wn = wid % WGN;
    const int bm0 = blockIdx.y * BM, bn0 = blockIdx.x * BN;

    wmma::fragment<wmma::accumulator, 16, 16, 8, float> acc[FM][4];
#pragma unroll
    for (int i = 0; i < FM; i++)
#pragma unroll
        for (int j = 0; j < 4; j++) wmma::fill_fragment(acc[i][j], 0.0f);

    auto load_tile = [&](int stage, int k0) {
        float* Ad = As + stage * A_STG;
        float* Bd = Bs + stage * B_STG;
#pragma unroll
        for (int i = tid; i < BM * (BK / 4); i += 256) {
            int r = i >> 3, c = (i & 7) * 4;
            cp_async16(Ad + r * LDA + c, A + (size_t)(bm0 + r) * Kdim + k0 + c);
        }
#pragma unroll
        for (int i = tid; i < BK * (BN / 4); i += 256) {
            int r = i / (BN / 4), c = (i % (BN / 4)) * 4;
            cp_async16(Bd + r * LDB + c, Bw + (size_t)(k0 + r) * Ndim + bn0 + c);
        }
    };

    const int KT = Kdim / BK;
#pragma unroll
    for (int s = 0; s < STAGES - 1; ++s) {
        if (s < KT) load_tile(s, s * BK);
        cp_commit();
    }

    int read = 0, write = STAGES - 1;
    for (int it = 0; it < KT; ++it) {
        asm volatile("cp.async.wait_group %0;\n" :: "n"(STAGES - 2));
        __syncthreads();
        int knext = (it + STAGES - 1) * BK;
        if (knext < Kdim) load_tile(write, knext);
        cp_commit();

        const float* Asr = As + read * A_STG;
        const float* Bsr = Bs + read * B_STG;
#pragma unroll
        for (int kk = 0; kk < BK; kk += 8) {
            wmma::fragment<wmma::matrix_a, 16, 16, 8, wmma::precision::tf32, wmma::row_major> af[FM];
            wmma::fragment<wmma::matrix_b, 16, 16, 8, wmma::precision::tf32, wmma::row_major> bf[4];
#pragma unroll
            for (int i = 0; i < FM; i++) {
                wmma::load_matrix_sync(af[i], Asr + (wm * WTM + i * 16) * LDA + kk, LDA);
#pragma unroll
                for (int t = 0; t < af[i].num_elements; t++) af[i].x[t] = to_tf32(af[i].x[t]);
            }
#pragma unroll
            for (int j = 0; j < 4; j++) {
                wmma::load_matrix_sync(bf[j], Bsr + kk * LDB + wn * 64 + j * 16, LDB);
#pragma unroll
                for (int t = 0; t < bf[j].num_elements; t++) bf[j].x[t] = to_tf32(bf[j].x[t]);
            }
#pragma unroll
            for (int i = 0; i < FM; i++)
#pragma unroll
                for (int j = 0; j < 4; j++)
                    wmma::mma_sync(acc[i][j], af[i], bf[j], acc[i][j]);
        }
        read = (read + 1) % STAGES;
        write = (write + 1) % STAGES;
    }

    asm volatile("cp.async.wait_group 0;\n" ::);
    __syncthreads();

    float* Cs = sm;
#pragma unroll
    for (int i = 0; i < FM; i++)
#pragma unroll
        for (int j = 0; j < 4; j++)
            wmma::store_matrix_sync(Cs + (wm * WTM + i * 16) * LDB + wn * 64 + j * 16,
                                    acc[i][j], LDB, wmma::mem_row_major);
    __syncthreads();

#pragma unroll 4
    for (int i = tid; i < BM * (BN / 4); i += 256) {
        int r = i / (BN / 4), c = (i % (BN / 4)) * 4;
        float4 v = *(float4*)&Cs[r * LDB + c];
        float4 bb = *(const float4*)(bias + bn0 + c);
        v.x += bb.x; v.y += bb.y; v.z += bb.z; v.w += bb.w;
        if (EPI == EPI_GELU) {
            v.x = 0.5f * v.x * (1.0f + erff(v.x * 0.70710678118654752f));
            v.y = 0.5f * v.y * (1.0f + erff(v.y * 0.70710678118654752f));
            v.z = 0.5f * v.z * (1.0f + erff(v.z * 0.70710678118654752f));
            v.w = 0.5f * v.w * (1.0f + erff(v.w * 0.70710678118654752f));
        }
        if (EPI == EPI_RES) {
            float4 rr = *(const float4*)(Rres + (size_t)(bm0 + r) * Ndim + bn0 + c);
            v.x += rr.x; v.y += rr.y; v.z += rr.z; v.w += rr.w;
        }
        *(float4*)(C + (size_t)(bm0 + r) * Ndim + bn0 + c) = v;
    }
}

// ---------------- fused flash attention ----------------
// Per CTA: 64 query rows for one (b,h). Key insight: logits = -g*d with d>=0 and
// d(q,q)=0, so the per-row max logit is exactly 0 -> p=exp(s) directly, no online
// max, no O rescaling. P tile lives only in smem; exp via FMA-pipe polynomial.
// Smem layout (floats):
//   zq  [64][20]     query coords
//   qsq [64]
//   zks [128][20]    key coords (row-major)
//   ksq [128]
//   P   [64][132]    exp(logits), tf32-rounded; reused as C-tile in epilogue
//   Vs  [128][68]    V tile, tf32-rounded
//   linv[64]
#define ATT_ZQ   0
#define ATT_QSQ  (ATT_ZQ + 64*20)
#define ATT_ZKS  (ATT_QSQ + 64)
#define ATT_KSQ  (ATT_ZKS + 128*20)
#define ATT_P    (ATT_KSQ + 128)
#define ATT_VS   (ATT_P + 64*132)
#define ATT_LINV (ATT_VS + 128*68)
#define ATT_SM_FLOATS (ATT_LINV + 64)

__global__ void __launch_bounds__(256, 2) attn_fused(
    const float* __restrict__ zh, const float* __restrict__ gamma,
    const float* __restrict__ V, float* __restrict__ O)
{
    extern __shared__ float sm[];
    float* zq   = sm + ATT_ZQ;
    float* qsq  = sm + ATT_QSQ;
    float* zks  = sm + ATT_ZKS;
    float* ksq  = sm + ATT_KSQ;
    float* P    = sm + ATT_P;
    float* Vs   = sm + ATT_VS;
    float* linv = sm + ATT_LINV;

    const int tid = threadIdx.x;
    const int wid = tid >> 5;
    const int bh = blockIdx.y;
    const int b = bh >> 4, h = bh & 15;
    const int q0 = blockIdx.x * 64;

    const float gx = gamma[h];
    const float g = (gx > 20.f) ? gx : log1pf(__expf(gx));

    // load zq tile [64 x 16]
    for (int i = tid; i < 64 * 4; i += 256) {
        int r = i >> 2, c = (i & 3) * 4;
        float4 v = *(const float4*)(zh + ((size_t)(b * S_ + q0 + r)) * (H_ * HC_) + h * HC_ + c);
        *(float4*)&zq[r * 20 + c] = v;
    }
    __syncthreads();
    if (tid < 64) {
        float s = 0.f;
#pragma unroll
        for (int c = 0; c < 16; c++) { float v = zq[tid * 20 + c]; s = fmaf(v, v, s); }
        qsq[tid] = s;
    }
    __syncthreads();

    // per-thread query registers: row = tid/4, col slots = (tid&3) + 4j
    const int row = tid >> 2;
    const int s4  = tid & 3;
    float zqr[16];
#pragma unroll
    for (int c = 0; c < 16; c++) zqr[c] = zq[row * 20 + c];
    const float qsq_r = qsq[row];
    float rowsum = 0.f;

    // PV accumulators: warp (wm,wn) owns rows 16*wm.., cols 32*wn..
    const int wm = wid >> 1, wn = wid & 1;
    wmma::fragment<wmma::accumulator, 16, 16, 8, float> acc[2];
    wmma::fill_fragment(acc[0], 0.0f);
    wmma::fill_fragment(acc[1], 0.0f);

    const float* Vb = V + (size_t)b * S_ * D_ + h * DH_;

    for (int k0 = 0; k0 < S_; k0 += 128) {
        __syncthreads();   // previous tile's P/Vs fully consumed
        // load key tile [128 x 16]
        for (int i = tid; i < 128 * 4; i += 256) {
            int r = i >> 2, c = (i & 3) * 4;
            float4 v = *(const float4*)(zh + ((size_t)(b * S_ + k0 + r)) * (H_ * HC_) + h * HC_ + c);
            *(float4*)&zks[r * 20 + c] = v;
        }
        // load V tile [128 x 64], tf32-rounded
        for (int i = tid; i < 128 * 16; i += 256) {
            int r = i >> 4, c = (i & 15) * 4;
            float4 v = *(const float4*)(Vb + (size_t)(k0 + r) * D_ + c);
            v.x = to_tf32(v.x); v.y = to_tf32(v.y); v.z = to_tf32(v.z); v.w = to_tf32(v.w);
            *(float4*)&Vs[r * 68 + c] = v;
        }
        __syncthreads();
        if (tid < 128) {
            float s = 0.f;
#pragma unroll
            for (int c = 0; c < 16; c++) { float v = zks[tid * 20 + c]; s = fmaf(v, v, s); }
            ksq[tid] = s;
        }
        __syncthreads();

        // P[row][col] = exp(-g * max(qsq+ksq-2dot, 0)), cols (s4 + 4j)
#pragma unroll 4
        for (int j = 0; j < 32; j++) {
            int col = s4 + 4 * j;
            const float* zk = &zks[col * 20];
            float4 a0 = *(const float4*)(zk + 0);
            float4 a1 = *(const float4*)(zk + 4);
            float4 a2 = *(const float4*)(zk + 8);
            float4 a3 = *(const float4*)(zk + 12);
            float dot = 0.f;
            dot = fmaf(zqr[0], a0.x, dot);  dot = fmaf(zqr[1], a0.y, dot);
            dot = fmaf(zqr[2], a0.z, dot);  dot = fmaf(zqr[3], a0.w, dot);
            dot = fmaf(zqr[4], a1.x, dot);  dot = fmaf(zqr[5], a1.y, dot);
            dot = fmaf(zqr[6], a1.z, dot);  dot = fmaf(zqr[7], a1.w, dot);
            dot = fmaf(zqr[8], a2.x, dot);  dot = fmaf(zqr[9], a2.y, dot);
            dot = fmaf(zqr[10], a2.z, dot); dot = fmaf(zqr[11], a2.w, dot);
            dot = fmaf(zqr[12], a3.x, dot); dot = fmaf(zqr[13], a3.y, dot);
            dot = fmaf(zqr[14], a3.z, dot); dot = fmaf(zqr[15], a3.w, dot);
            float d = fmaxf(qsq_r + ksq[col] - 2.f * dot, 0.f);
            float p = fast_exp_neg(-g * d);
            rowsum += p;
            P[row * 132 + col] = to_tf32(p);
        }
        __syncthreads();

        // O += P @ V  (warp tile 16x32)
#pragma unroll
        for (int ks = 0; ks < 128; ks += 8) {
            wmma::fragment<wmma::matrix_a, 16, 16, 8, wmma::precision::tf32, wmma::row_major> af;
            wmma::load_matrix_sync(af, P + (16 * wm) * 132 + ks, 132);
#pragma unroll
            for (int f = 0; f < 2; f++) {
                wmma::fragment<wmma::matrix_b, 16, 16, 8, wmma::precision::tf32, wmma::row_major> bf;
                wmma::load_matrix_sync(bf, Vs + ks * 68 + 32 * wn + 16 * f, 68);
                wmma::mma_sync(acc[f], af, bf, acc[f]);
            }
        }
    }

    // reduce row sums across the 4 threads of each row (adjacent lanes)
    rowsum += __shfl_xor_sync(0xffffffffu, rowsum, 1);
    rowsum += __shfl_xor_sync(0xffffffffu, rowsum, 2);
    __syncthreads();             // final MMA reads of P done
    if (s4 == 0) linv[row] = 1.0f / rowsum;
    // store accumulators into P region as C tile (ld 132)
    wmma::store_matrix_sync(P + (16 * wm) * 132 + 32 * wn,      acc[0], 132, wmma::mem_row_major);
    wmma::store_matrix_sync(P + (16 * wm) * 132 + 32 * wn + 16, acc[1], 132, wmma::mem_row_major);
    __syncthreads();

    // epilogue: O[b, q0+r, h*64 + c] = C[r][c] * linv[r]
    for (int i = tid; i < 64 * 16; i += 256) {
        int r = i >> 4, c = (i & 15) * 4;
        float4 v = *(float4*)&P[r * 132 + c];
        float li = linv[r];
        v.x *= li; v.y *= li; v.z *= li; v.w *= li;
        *(float4*)(O + ((size_t)(b * S_ + q0 + r)) * D_ + h * DH_ + c) = v;
    }
}

// ---------------- LayerNorm over last dim ----------------
__global__ void ln_kernel(const float* __restrict__ x, const float* __restrict__ gm,
                          const float* __restrict__ bt, float* __restrict__ y, int Dd)
{
    const int row = blockIdx.x;
    const float* xr = x + (size_t)row * Dd;
    float s = 0.f, s2 = 0.f;
    for (int i = threadIdx.x; i < Dd; i += blockDim.x) {
        float v = xr[i]; s += v; s2 = fmaf(v, v, s2);
    }
    __shared__ float red[2][32];
    const int lane = threadIdx.x & 31, wid = threadIdx.x >> 5;
#pragma unroll
    for (int off = 16; off; off >>= 1) {
        s  += __shfl_xor_sync(0xffffffffu, s, off);
        s2 += __shfl_xor_sync(0xffffffffu, s2, off);
    }
    if (lane == 0) { red[0][wid] = s; red[1][wid] = s2; }
    __syncthreads();
    const int nw = blockDim.x >> 5;
    if (wid == 0) {
        s  = (lane < nw) ? red[0][lane] : 0.f;
        s2 = (lane < nw) ? red[1][lane] : 0.f;
#pragma unroll
        for (int off = 16; off; off >>= 1) {
            s  += __shfl_xor_sync(0xffffffffu, s, off);
            s2 += __shfl_xor_sync(0xffffffffu, s2, off);
        }
        if (lane == 0) { red[0][0] = s; red[1][0] = s2; }
    }
    __syncthreads();
    s = red[0][0]; s2 = red[1][0];
    const float mean = s / Dd;
    const float var  = s2 / Dd - mean * mean;
    const float inv  = rsqrtf(var + 1e-5f);
    float* yr = y + (size_t)row * Dd;
    for (int i = threadIdx.x; i < Dd; i += blockDim.x)
        yr[i] = (xr[i] - mean) * inv * gm[i] + bt[i];
}

// ---------------- launch ----------------
extern "C" void kernel_launch(void* const* d_in, const int* in_sizes, int n_in,
                              void* d_out, int out_size)
{
    const float* h    = (const float*)d_in[0];
    const float* z    = (const float*)d_in[1];
    const float* wv   = (const float*)d_in[2];
    const float* bv   = (const float*)d_in[3];
    const float* wca  = (const float*)d_in[4];
    const float* bca  = (const float*)d_in[5];
    const float* wcn  = (const float*)d_in[6];
    const float* bcn  = (const float*)d_in[7];
    const float* wo   = (const float*)d_in[8];
    const float* bo   = (const float*)d_in[9];
    const float* gamma= (const float*)d_in[10];
    const float* w1   = (const float*)d_in[11];
    const float* b1   = (const float*)d_in[12];
    const float* w2   = (const float*)d_in[13];
    const float* b2   = (const float*)d_in[14];
    const float* ln1g = (const float*)d_in[15];
    const float* ln1b = (const float*)d_in[16];
    const float* ln2g = (const float*)d_in[17];
    const float* ln2b = (const float*)d_in[18];
    const float* lncg = (const float*)d_in[19];
    const float* lncb = (const float*)d_in[20];

    float* out_h = (float*)d_out;
    float* out_z = out_h + (size_t)BS_ * D_;

    float *p_hn, *p_val, *p_zh, *p_attn, *p_h1, *p_hn2, *p_mid, *p_ztmp;
    cudaGetSymbolAddress((void**)&p_hn,  g_hn);
    cudaGetSymbolAddress((void**)&p_val, g_val);
    cudaGetSymbolAddress((void**)&p_zh,  g_zh);
    cudaGetSymbolAddress((void**)&p_attn,g_attn);
    cudaGetSymbolAddress((void**)&p_h1,  g_h1);
    cudaGetSymbolAddress((void**)&p_hn2, g_hn2);
    cudaGetSymbolAddress((void**)&p_mid, g_mid);
    cudaGetSymbolAddress((void**)&p_ztmp,g_ztmp);

    constexpr int SM128 = 3 * (128 * 36 + 32 * 132) * 4;   // 105984 B
    constexpr int SM64  = 3 * (128 * 36 + 32 * 68) * 4;    //  81408 B
    constexpr int SMATT = ATT_SM_FLOATS * 4;               //  ~85 KB
    cudaFuncSetAttribute(gemm_pipe<128,128,EPI_BIAS>, cudaFuncAttributeMaxDynamicSharedMemorySize, SM128);
    cudaFuncSetAttribute(gemm_pipe<128,128,EPI_RES >, cudaFuncAttributeMaxDynamicSharedMemorySize, SM128);
    cudaFuncSetAttribute(gemm_pipe<128,128,EPI_GELU>, cudaFuncAttributeMaxDynamicSharedMemorySize, SM128);
    cudaFuncSetAttribute(gemm_pipe<128, 64,EPI_RES >, cudaFuncAttributeMaxDynamicSharedMemorySize, SM64);
    cudaFuncSetAttribute(attn_fused, cudaFuncAttributeMaxDynamicSharedMemorySize, SMATT);

    // 1) hn = LN1(h)
    ln_kernel<<<BS_, 256>>>(h, ln1g, ln1b, p_hn, D_);
    // 2) value = hn @ wv + bv
    gemm_pipe<128,128,EPI_BIAS><<<dim3(D_/128, BS_/128), 256, SM128>>>(p_hn, wv, bv, nullptr, p_val, BS_, D_, D_);
    // 3) zh = z @ wca + bca
    gemm_pipe<128,128,EPI_BIAS><<<dim3(256/128, BS_/128), 256, SM128>>>(z, wca, bca, nullptr, p_zh, BS_, 256, DC_);
    // 4) z_tmp = z + (hn @ wcn + bcn)
    gemm_pipe<128,64,EPI_RES><<<dim3(1, BS_/128), 256, SM64>>>(p_hn, wcn, bcn, z, p_ztmp, BS_, DC_, D_);
    // 5+6) fused attention: attn_out = softmax(-g*dist) @ V
    attn_fused<<<dim3(S_/64, BH_), 256, SMATT>>>(p_zh, gamma, p_val, p_attn);
    // 7) h1 = h + (attn_out @ wo + bo)
    gemm_pipe<128,128,EPI_RES><<<dim3(D_/128, BS_/128), 256, SM128>>>(p_attn, wo, bo, h, p_h1, BS_, D_, D_);
    // 8) hn2 = LN2(h1)
    ln_kernel<<<BS_, 256>>>(p_h1, ln2g, ln2b, p_hn2, D_);
    // 9) mid = gelu(hn2 @ w1 + b1)
    gemm_pipe<128,128,EPI_GELU><<<dim3(MFF_/128, BS_/128), 256, SM128>>>(p_hn2, w1, b1, nullptr, p_mid, BS_, MFF_, D_);
    // 10) out_h = h1 + (mid @ w2 + b2)
    gemm_pipe<128,128,EPI_RES><<<dim3(D_/128, BS_/128), 256, SM128>>>(p_mid, w2, b2, p_h1, out_h, BS_, D_, MFF_);
    // 11) out_z = LN_c(z_tmp)
    ln_kernel<<<BS_, 64>>>(p_ztmp, lncg, lncb, out_z, DC_);
}

// round 10
// speedup vs baseline: 1.5893x; 1.5893x over previous
#include <cuda_runtime.h>
#include <mma.h>
#include <math.h>

using namespace nvcuda;

#define B_   2
#define S_   2048
#define D_   1024
#define H_   16
#define DC_  64
#define HC_  16
#define MFF_ 4096
#define DH_  64
#define BS_  (B_*S_)      // 4096
#define BH_  (B_*H_)      // 32

// ---------------- scratch (static device globals; no allocation) ----------------
__device__ float g_hn  [BS_*D_];
__device__ float g_val [BS_*D_];
__device__ float g_zh  [BS_*H_*HC_];
__device__ float g_P   [134217728];   // B*H*S*S  exp(logits), tf32-rounded
__device__ float g_rowl[BH_*S_];
__device__ float g_attn[BS_*D_];
__device__ float g_h1  [BS_*D_];
__device__ float g_hn2 [BS_*D_];
__device__ float g_mid [BS_*MFF_];
__device__ float g_ztmp[BS_*DC_];

__device__ __forceinline__ float to_tf32(float x) {
    float r; asm("cvt.rna.tf32.f32 %0, %1;" : "=f"(r) : "f"(x)); return r;
}

// exp(s) for s <= 0, FMA-pipe only (no MUFU). ~2.4e-6 max rel err.
__device__ __forceinline__ float fast_exp_neg(float s) {
    float y = fmaxf(s * 1.4426950408889634f, -126.0f);   // log2(e)*s, clamped
    float z = y + 12582912.0f;                           // round-to-nearest int (1.5*2^23)
    float r = z - 12582912.0f;
    float f = y - r;                                     // f in [-0.5, 0.5]
    int   iz = __float_as_int(z);
    float sc = __int_as_float((iz + (127 - 0x400000)) << 23);   // 2^round(y)
    float p = 0.0013333558f;
    p = fmaf(p, f, 0.0096181291f);
    p = fmaf(p, f, 0.0555041087f);
    p = fmaf(p, f, 0.2402265070f);
    p = fmaf(p, f, 0.6931471806f);
    p = fmaf(p, f, 1.0f);
    return sc * p;
}

enum { EPI_BIAS = 0, EPI_RES = 1, EPI_GELU = 2, EPI_BIAS_RND = 3 };

__device__ __forceinline__ void cp_async16(float* smem_dst, const float* gmem_src) {
    unsigned sa = (unsigned)__cvta_generic_to_shared(smem_dst);
    asm volatile("cp.async.cg.shared.global [%0], [%1], 16;\n" :: "r"(sa), "l"(gmem_src));
}
__device__ __forceinline__ void cp_commit() {
    asm volatile("cp.async.commit_group;\n" ::);
}

// ---------------- pipelined tf32 GEMM: C = epi(A[M,K] @ B[K,N] + bias) ----------------
template<int BM, int BN, int EPI>
__global__ void __launch_bounds__(256, 2) gemm_pipe(
    const float* __restrict__ A, const float* __restrict__ Bw,
    const float* __restrict__ bias, const float* __restrict__ Rres,
    float* __restrict__ C, int Mdim, int Ndim, int Kdim)
{
    constexpr int BK = 32;
    constexpr int STAGES = 3;
    constexpr int LDA = BK + 4;
    constexpr int LDB = BN + 4;
    constexpr int WGN = BN / 64;
    constexpr int WGM = 8 / WGN;
    constexpr int WTM = BM / WGM;
    constexpr int FM  = WTM / 16;
    constexpr int A_STG = BM * LDA;
    constexpr int B_STG = BK * LDB;

    extern __shared__ float sm[];
    float* As = sm;
    float* Bs = sm + STAGES * A_STG;

    const int tid = threadIdx.x;
    const int wid = tid >> 5;
    const int wm = wid / WGN, wn = wid % WGN;
    const int bm0 = blockIdx.y * BM, bn0 = blockIdx.x * BN;

    wmma::fragment<wmma::accumulator, 16, 16, 8, float> acc[FM][4];
#pragma unroll
    for (int i = 0; i < FM; i++)
#pragma unroll
        for (int j = 0; j < 4; j++) wmma::fill_fragment(acc[i][j], 0.0f);

    auto load_tile = [&](int stage, int k0) {
        float* Ad = As + stage * A_STG;
        float* Bd = Bs + stage * B_STG;
#pragma unroll
        for (int i = tid; i < BM * (BK / 4); i += 256) {
            int r = i >> 3, c = (i & 7) * 4;
            cp_async16(Ad + r * LDA + c, A + (size_t)(bm0 + r) * Kdim + k0 + c);
        }
#pragma unroll
        for (int i = tid; i < BK * (BN / 4); i += 256) {
            int r = i / (BN / 4), c = (i % (BN / 4)) * 4;
            cp_async16(Bd + r * LDB + c, Bw + (size_t)(k0 + r) * Ndim + bn0 + c);
        }
    };

    const int KT = Kdim / BK;
#pragma unroll
    for (int s = 0; s < STAGES - 1; ++s) {
        if (s < KT) load_tile(s, s * BK);
        cp_commit();
    }

    int read = 0, write = STAGES - 1;
    for (int it = 0; it < KT; ++it) {
        asm volatile("cp.async.wait_group %0;\n" :: "n"(STAGES - 2));
        __syncthreads();
        int knext = (it + STAGES - 1) * BK;
        if (knext < Kdim) load_tile(write, knext);
        cp_commit();

        const float* Asr = As + read * A_STG;
        const float* Bsr = Bs + read * B_STG;
#pragma unroll
        for (int kk = 0; kk < BK; kk += 8) {
            wmma::fragment<wmma::matrix_a, 16, 16, 8, wmma::precision::tf32, wmma::row_major> af[FM];
            wmma::fragment<wmma::matrix_b, 16, 16, 8, wmma::precision::tf32, wmma::row_major> bf[4];
#pragma unroll
            for (int i = 0; i < FM; i++) {
                wmma::load_matrix_sync(af[i], Asr + (wm * WTM + i * 16) * LDA + kk, LDA);
#pragma unroll
                for (int t = 0; t < af[i].num_elements; t++) af[i].x[t] = to_tf32(af[i].x[t]);
            }
#pragma unroll
            for (int j = 0; j < 4; j++) {
                wmma::load_matrix_sync(bf[j], Bsr + kk * LDB + wn * 64 + j * 16, LDB);
#pragma unroll
                for (int t = 0; t < bf[j].num_elements; t++) bf[j].x[t] = to_tf32(bf[j].x[t]);
            }
#pragma unroll
            for (int i = 0; i < FM; i++)
#pragma unroll
                for (int j = 0; j < 4; j++)
                    wmma::mma_sync(acc[i][j], af[i], bf[j], acc[i][j]);
        }
        read = (read + 1) % STAGES;
        write = (write + 1) % STAGES;
    }

    asm volatile("cp.async.wait_group 0;\n" ::);
    __syncthreads();

    float* Cs = sm;
#pragma unroll
    for (int i = 0; i < FM; i++)
#pragma unroll
        for (int j = 0; j < 4; j++)
            wmma::store_matrix_sync(Cs + (wm * WTM + i * 16) * LDB + wn * 64 + j * 16,
                                    acc[i][j], LDB, wmma::mem_row_major);
    __syncthreads();

#pragma unroll 4
    for (int i = tid; i < BM * (BN / 4); i += 256) {
        int r = i / (BN / 4), c = (i % (BN / 4)) * 4;
        float4 v = *(float4*)&Cs[r * LDB + c];
        float4 bb = *(const float4*)(bias + bn0 + c);
        v.x += bb.x; v.y += bb.y; v.z += bb.z; v.w += bb.w;
        if (EPI == EPI_GELU) {
            v.x = 0.5f * v.x * (1.0f + erff(v.x * 0.70710678118654752f));
            v.y = 0.5f * v.y * (1.0f + erff(v.y * 0.70710678118654752f));
            v.z = 0.5f * v.z * (1.0f + erff(v.z * 0.70710678118654752f));
            v.w = 0.5f * v.w * (1.0f + erff(v.w * 0.70710678118654752f));
        }
        if (EPI == EPI_RES) {
            float4 rr = *(const float4*)(Rres + (size_t)(bm0 + r) * Ndim + bn0 + c);
            v.x += rr.x; v.y += rr.y; v.z += rr.z; v.w += rr.w;
        }
        if (EPI == EPI_BIAS_RND) {
            v.x = to_tf32(v.x); v.y = to_tf32(v.y); v.z = to_tf32(v.z); v.w = to_tf32(v.w);
        }
        *(float4*)(C + (size_t)(bm0 + r) * Ndim + bn0 + c) = v;
    }
}

// ---------------- distance scores: P = tf32(exp(-g*dist)), rowl = row sums -----
// Row max is exactly 0 (diagonal distance = 0), so exp(s) is stable directly:
// no online max, no branches, no MUFU.
__global__ void __launch_bounds__(256, 2) score_kernel(
    const float* __restrict__ zh, const float* __restrict__ gamma,
    float* __restrict__ P, float* __restrict__ rowl)
{
    __shared__ float zqs[64][17];
    __shared__ float zkt[16][132];
    __shared__ float ksq[128];

    const int b = blockIdx.z, h = blockIdx.y;
    const int q0 = blockIdx.x * 64;
    const int tid = threadIdx.x;
    const float gx = gamma[h];
    const float g = (gx > 20.f) ? gx : log1pf(__expf(gx));

    for (int i = tid; i < 64 * 4; i += 256) {
        int r = i >> 2, c = (i & 3) * 4;
        float4 v = *(const float4*)(zh + ((size_t)(b * S_ + q0 + r)) * (H_ * HC_) + h * HC_ + c);
        zqs[r][c] = v.x; zqs[r][c + 1] = v.y; zqs[r][c + 2] = v.z; zqs[r][c + 3] = v.w;
    }
    __syncthreads();

    const int qg = tid >> 4;      // 16 groups of 4 queries
    const int kslot = tid & 15;
    float zq[4][16], qsq[4], l[4];
#pragma unroll
    for (int qi = 0; qi < 4; qi++) {
        float s = 0.f;
#pragma unroll
        for (int c = 0; c < 16; c++) { float v = zqs[qg * 4 + qi][c]; zq[qi][c] = v; s = fmaf(v, v, s); }
        qsq[qi] = s; l[qi] = 0.f;
    }

    const int bh = b * H_ + h;
    const size_t prow0 = ((size_t)bh * S_ + (q0 + qg * 4)) * S_;

    for (int k0 = 0; k0 < S_; k0 += 128) {
        __syncthreads();
        for (int i = tid; i < 128 * 4; i += 256) {
            int r = i >> 2, c = (i & 3) * 4;
            float4 v = *(const float4*)(zh + ((size_t)(b * S_ + k0 + r)) * (H_ * HC_) + h * HC_ + c);
            zkt[c][r] = v.x; zkt[c + 1][r] = v.y; zkt[c + 2][r] = v.z; zkt[c + 3][r] = v.w;
        }
        __syncthreads();
        if (tid < 128) {
            float s = 0.f;
#pragma unroll
            for (int c = 0; c < 16; c++) { float v = zkt[c][tid]; s = fmaf(v, v, s); }
            ksq[tid] = s;
        }
        __syncthreads();
#pragma unroll
        for (int j = 0; j < 8; j++) {
            int kk = j * 16 + kslot;
            float zk[16];
#pragma unroll
            for (int c = 0; c < 16; c++) zk[c] = zkt[c][kk];
            float kq = ksq[kk];
#pragma unroll
            for (int qi = 0; qi < 4; qi++) {
                float dot = 0.f;
#pragma unroll
                for (int c = 0; c < 16; c++) dot = fmaf(zq[qi][c], zk[c], dot);
                float d = fmaxf(qsq[qi] + kq - 2.f * dot, 0.f);
                float p = fast_exp_neg(-g * d);
                l[qi] += p;
                P[prow0 + (size_t)qi * S_ + k0 + kk] = to_tf32(p);
            }
        }
    }
    // reduce l over the 16 kslots of this query group
#pragma unroll
    for (int off = 8; off > 0; off >>= 1) {
#pragma unroll
        for (int qi = 0; qi < 4; qi++)
            l[qi] += __shfl_xor_sync(0xffffffffu, l[qi], off);
    }
    if (kslot == 0) {
#pragma unroll
        for (int qi = 0; qi < 4; qi++)
            rowl[bh * S_ + q0 + qg * 4 + qi] = l[qi];
    }
}

// ---------------- PV: O = (P @ V) * (1/rowl), pipelined pure tf32 GEMM ----------
// P and V are both already tf32-rounded in gmem -> no cvts anywhere.
__global__ void __launch_bounds__(256, 2) pv_pipe(
    const float* __restrict__ P, const float* __restrict__ rowl,
    const float* __restrict__ V, float* __restrict__ O)
{
    constexpr int BM = 128, BN = 64, BK = 32, STAGES = 3;
    constexpr int LDA = BK + 4, LDB = BN + 4;
    constexpr int A_STG = BM * LDA;   // 4608
    constexpr int B_STG = BK * LDB;   // 2176

    extern __shared__ float sm[];
    float* As = sm;
    float* Bs = sm + STAGES * A_STG;
    float* linv = sm + STAGES * (A_STG + B_STG);   // 128 floats

    const int tid = threadIdx.x;
    const int wid = tid >> 5;
    const int bh = blockIdx.y;
    const int b = bh >> 4, h = bh & 15;
    const int q0 = blockIdx.x * BM;

    const float* Ab = P + (size_t)bh * S_ * S_;            // rows q0+r, ld S_
    const float* Bb = V + (size_t)b * S_ * D_ + h * DH_;   // rows k, ld D_

    if (tid < BM) linv[tid] = 1.0f / rowl[bh * S_ + q0 + tid];

    wmma::fragment<wmma::accumulator, 16, 16, 8, float> acc[4];
#pragma unroll
    for (int j = 0; j < 4; j++) wmma::fill_fragment(acc[j], 0.0f);

    auto load_tile = [&](int stage, int k0) {
        float* Ad = As + stage * A_STG;
        float* Bd = Bs + stage * B_STG;
#pragma unroll
        for (int i = tid; i < BM * 8; i += 256) {
            int r = i >> 3, c = (i & 7) * 4;
            cp_async16(Ad + r * LDA + c, Ab + (size_t)(q0 + r) * S_ + k0 + c);
        }
#pragma unroll
        for (int i = tid; i < BK * 16; i += 256) {
            int r = i >> 4, c = (i & 15) * 4;
            cp_async16(Bd + r * LDB + c, Bb + (size_t)(k0 + r) * D_ + c);
        }
    };

    constexpr int KT = S_ / BK;   // 64
#pragma unroll
    for (int s = 0; s < STAGES - 1; ++s) {
        load_tile(s, s * BK);
        cp_commit();
    }

    int read = 0, write = STAGES - 1;
    for (int it = 0; it < KT; ++it) {
        asm volatile("cp.async.wait_group %0;\n" :: "n"(STAGES - 2));
        __syncthreads();
        int knext = (it + STAGES - 1) * BK;
        if (knext < S_) load_tile(write, knext);
        cp_commit();

        const float* Asr = As + read * A_STG;
        const float* Bsr = Bs + read * B_STG;
#pragma unroll
        for (int kk = 0; kk < BK; kk += 8) {
            wmma::fragment<wmma::matrix_a, 16, 16, 8, wmma::precision::tf32, wmma::row_major> af;
            wmma::load_matrix_sync(af, Asr + (wid * 16) * LDA + kk, LDA);
#pragma unroll
            for (int j = 0; j < 4; j++) {
                wmma::fragment<wmma::matrix_b, 16, 16, 8, wmma::precision::tf32, wmma::row_major> bf;
                wmma::load_matrix_sync(bf, Bsr + kk * LDB + j * 16, LDB);
                wmma::mma_sync(acc[j], af, bf, acc[j]);
            }
        }
        read = (read + 1) % STAGES;
        write = (write + 1) % STAGES;
    }

    asm volatile("cp.async.wait_group 0;\n" ::);
    __syncthreads();

    float* Cs = sm;   // 128 x 68
#pragma unroll
    for (int j = 0; j < 4; j++)
        wmma::store_matrix_sync(Cs + (wid * 16) * LDB + j * 16, acc[j], LDB, wmma::mem_row_major);
    __syncthreads();

#pragma unroll 4
    for (int i = tid; i < BM * 16; i += 256) {
        int r = i >> 4, c = (i & 15) * 4;
        float4 v = *(float4*)&Cs[r * LDB + c];
        float li = linv[r];
        v.x *= li; v.y *= li; v.z *= li; v.w *= li;
        *(float4*)(O + ((size_t)(b * S_ + q0 + r)) * D_ + h * DH_ + c) = v;
    }
}

// ---------------- LayerNorm over last dim ----------------
__global__ void ln_kernel(const float* __restrict__ x, const float* __restrict__ gm,
                          const float* __restrict__ bt, float* __restrict__ y, int Dd)
{
    const int row = blockIdx.x;
    const float* xr = x + (size_t)row * Dd;
    float s = 0.f, s2 = 0.f;
    for (int i = threadIdx.x; i < Dd; i += blockDim.x) {
        float v = xr[i]; s += v; s2 = fmaf(v, v, s2);
    }
    __shared__ float red[2][32];
    const int lane = threadIdx.x & 31, wid = threadIdx.x >> 5;
#pragma unroll
    for (int off = 16; off; off >>= 1) {
        s  += __shfl_xor_sync(0xffffffffu, s, off);
        s2 += __shfl_xor_sync(0xffffffffu, s2, off);
    }
    if (lane == 0) { red[0][wid] = s; red[1][wid] = s2; }
    __syncthreads();
    const int nw = blockDim.x >> 5;
    if (wid == 0) {
        s  = (lane < nw) ? red[0][lane] : 0.f;
        s2 = (lane < nw) ? red[1][lane] : 0.f;
#pragma unroll
        for (int off = 16; off; off >>= 1) {
            s  += __shfl_xor_sync(0xffffffffu, s, off);
            s2 += __shfl_xor_sync(0xffffffffu, s2, off);
        }
        if (lane == 0) { red[0][0] = s; red[1][0] = s2; }
    }
    __syncthreads();
    s = red[0][0]; s2 = red[1][0];
    const float mean = s / Dd;
    const float var  = s2 / Dd - mean * mean;
    const float inv  = rsqrtf(var + 1e-5f);
    float* yr = y + (size_t)row * Dd;
    for (int i = threadIdx.x; i < Dd; i += blockDim.x)
        yr[i] = (xr[i] - mean) * inv * gm[i] + bt[i];
}

// ---------------- launch ----------------
extern "C" void kernel_launch(void* const* d_in, const int* in_sizes, int n_in,
                              void* d_out, int out_size)
{
    const float* h    = (const float*)d_in[0];
    const float* z    = (const float*)d_in[1];
    const float* wv   = (const float*)d_in[2];
    const float* bv   = (const float*)d_in[3];
    const float* wca  = (const float*)d_in[4];
    const float* bca  = (const float*)d_in[5];
    const float* wcn  = (const float*)d_in[6];
    const float* bcn  = (const float*)d_in[7];
    const float* wo   = (const float*)d_in[8];
    const float* bo   = (const float*)d_in[9];
    const float* gamma= (const float*)d_in[10];
    const float* w1   = (const float*)d_in[11];
    const float* b1   = (const float*)d_in[12];
    const float* w2   = (const float*)d_in[13];
    const float* b2   = (const float*)d_in[14];
    const float* ln1g = (const float*)d_in[15];
    const float* ln1b = (const float*)d_in[16];
    const float* ln2g = (const float*)d_in[17];
    const float* ln2b = (const float*)d_in[18];
    const float* lncg = (const float*)d_in[19];
    const float* lncb = (const float*)d_in[20];

    float* out_h = (float*)d_out;
    float* out_z = out_h + (size_t)BS_ * D_;

    float *p_hn, *p_val, *p_zh, *p_P, *p_rl, *p_attn, *p_h1, *p_hn2, *p_mid, *p_ztmp;
    cudaGetSymbolAddress((void**)&p_hn,  g_hn);
    cudaGetSymbolAddress((void**)&p_val, g_val);
    cudaGetSymbolAddress((void**)&p_zh,  g_zh);
    cudaGetSymbolAddress((void**)&p_P,   g_P);
    cudaGetSymbolAddress((void**)&p_rl,  g_rowl);
    cudaGetSymbolAddress((void**)&p_attn,g_attn);
    cudaGetSymbolAddress((void**)&p_h1,  g_h1);
    cudaGetSymbolAddress((void**)&p_hn2, g_hn2);
    cudaGetSymbolAddress((void**)&p_mid, g_mid);
    cudaGetSymbolAddress((void**)&p_ztmp,g_ztmp);

    constexpr int SM128 = 3 * (128 * 36 + 32 * 132) * 4;          // 105984 B
    constexpr int SM64  = 3 * (128 * 36 + 32 * 68) * 4;           //  81408 B
    constexpr int SMPV  = (3 * (128 * 36 + 32 * 68) + 128) * 4;   //  81920 B
    cudaFuncSetAttribute(gemm_pipe<128,128,EPI_BIAS>,     cudaFuncAttributeMaxDynamicSharedMemorySize, SM128);
    cudaFuncSetAttribute(gemm_pipe<128,128,EPI_BIAS_RND>, cudaFuncAttributeMaxDynamicSharedMemorySize, SM128);
    cudaFuncSetAttribute(gemm_pipe<128,128,EPI_RES >,     cudaFuncAttributeMaxDynamicSharedMemorySize, SM128);
    cudaFuncSetAttribute(gemm_pipe<128,128,EPI_GELU>,     cudaFuncAttributeMaxDynamicSharedMemorySize, SM128);
    cudaFuncSetAttribute(gemm_pipe<128, 64,EPI_RES >,     cudaFuncAttributeMaxDynamicSharedMemorySize, SM64);
    cudaFuncSetAttribute(pv_pipe,                         cudaFuncAttributeMaxDynamicSharedMemorySize, SMPV);

    // 1) hn = LN1(h)
    ln_kernel<<<BS_, 256>>>(h, ln1g, ln1b, p_hn, D_);
    // 2) value = tf32(hn @ wv + bv)   (rounded so PV can feed it raw)
    gemm_pipe<128,128,EPI_BIAS_RND><<<dim3(D_/128, BS_/128), 256, SM128>>>(p_hn, wv, bv, nullptr, p_val, BS_, D_, D_);
    // 3) zh = z @ wca + bca
    gemm_pipe<128,128,EPI_BIAS><<<dim3(256/128, BS_/128), 256, SM128>>>(z, wca, bca, nullptr, p_zh, BS_, 256, DC_);
    // 4) z_tmp = z + (hn @ wcn + bcn)
    gemm_pipe<128,64,EPI_RES><<<dim3(1, BS_/128), 256, SM64>>>(p_hn, wcn, bcn, z, p_ztmp, BS_, DC_, D_);
    // 5) P = tf32(exp(-g*dist)), rowl = row sums (max is exactly 0, no MUFU)
    score_kernel<<<dim3(S_/64, H_, B_), 256>>>(p_zh, gamma, p_P, p_rl);
    // 6) attn_out = (P @ V) / rowl   (pure pipelined tf32 GEMM, zero cvts)
    pv_pipe<<<dim3(S_/128, BH_), 256, SMPV>>>(p_P, p_rl, p_val, p_attn);
    // 7) h1 = h + (attn_out @ wo + bo)
    gemm_pipe<128,128,EPI_RES><<<dim3(D_/128, BS_/128), 256, SM128>>>(p_attn, wo, bo, h, p_h1, BS_, D_, D_);
    // 8) hn2 = LN2(h1)
    ln_kernel<<<BS_, 256>>>(p_h1, ln2g, ln2b, p_hn2, D_);
    // 9) mid = gelu(hn2 @ w1 + b1)
    gemm_pipe<128,128,EPI_GELU><<<dim3(MFF_/128, BS_/128), 256, SM128>>>(p_hn2, w1, b1, nullptr, p_mid, BS_, MFF_, D_);
    // 10) out_h = h1 + (mid @ w2 + b2)
    gemm_pipe<128,128,EPI_RES><<<dim3(D_/128, BS_/128), 256, SM128>>>(p_mid, w2, b2, p_h1, out_h, BS_, D_, MFF_);
    // 11) out_z = LN_c(z_tmp)
    ln_kernel<<<BS_, 64>>>(p_ztmp, lncg, lncb, out_z, DC_);
}

// round 11
// speedup vs baseline: 1.7155x; 1.0794x over previous
#include <cuda_runtime.h>
#include <mma.h>
#include <math.h>

using namespace nvcuda;

#define B_   2
#define S_   2048
#define D_   1024
#define H_   16
#define DC_  64
#define HC_  16
#define MFF_ 4096
#define DH_  64
#define BS_  (B_*S_)      // 4096
#define BH_  (B_*H_)      // 32

// ---------------- scratch (static device globals; no allocation) ----------------
__device__ float g_hn  [BS_*D_];
__device__ float g_val [BS_*D_];
__device__ float g_zh  [BS_*H_*HC_];
__device__ float g_P   [134217728];   // B*H*S*S  exp(logits), tf32-rounded
__device__ float g_rowl[BH_*S_];
__device__ float g_attn[BS_*D_];
__device__ float g_h1  [BS_*D_];
__device__ float g_hn2 [BS_*D_];
__device__ float g_mid [BS_*MFF_];
__device__ float g_ztmp[BS_*DC_];
// tf32-rounded operand copies (rounded once; mainloop has zero cvts)
__device__ float g_wv_r [D_*D_];
__device__ float g_wca_r[DC_*H_*HC_];
__device__ float g_wcn_r[D_*DC_];
__device__ float g_wo_r [D_*D_];
__device__ float g_w1_r [D_*MFF_];
__device__ float g_w2_r [MFF_*D_];
__device__ float g_z_r  [BS_*DC_];

__device__ __forceinline__ float to_tf32(float x) {
    float r; asm("cvt.rna.tf32.f32 %0, %1;" : "=f"(r) : "f"(x)); return r;
}

// exp(s) for s <= 0, FMA-pipe only (no MUFU). ~2.4e-6 max rel err.
__device__ __forceinline__ float fast_exp_neg(float s) {
    float y = fmaxf(s * 1.4426950408889634f, -126.0f);
    float z = y + 12582912.0f;
    float r = z - 12582912.0f;
    float f = y - r;
    int   iz = __float_as_int(z);
    float sc = __int_as_float((iz + (127 - 0x400000)) << 23);
    float p = 0.0013333558f;
    p = fmaf(p, f, 0.0096181291f);
    p = fmaf(p, f, 0.0555041087f);
    p = fmaf(p, f, 0.2402265070f);
    p = fmaf(p, f, 0.6931471806f);
    p = fmaf(p, f, 1.0f);
    return sc * p;
}

enum { EPI_BIAS = 0, EPI_RES = 1, EPI_GELU = 2, EPI_BIAS_RND = 3 };

__device__ __forceinline__ void cp_async16(float* smem_dst, const float* gmem_src) {
    unsigned sa = (unsigned)__cvta_generic_to_shared(smem_dst);
    asm volatile("cp.async.cg.shared.global [%0], [%1], 16;\n" :: "r"(sa), "l"(gmem_src));
}
__device__ __forceinline__ void cp_commit() {
    asm volatile("cp.async.commit_group;\n" ::);
}

// ---------------- elementwise tf32 rounding (float4) ----------------
__global__ void round_tf32_kernel(const float* __restrict__ x, float* __restrict__ y, int n4) {
    int i = blockIdx.x * blockDim.x + threadIdx.x;
    if (i < n4) {
        float4 v = ((const float4*)x)[i];
        v.x = to_tf32(v.x); v.y = to_tf32(v.y); v.z = to_tf32(v.z); v.w = to_tf32(v.w);
        ((float4*)y)[i] = v;
    }
}

// ---------------- pipelined tf32 GEMM: C = epi(A[M,K] @ B[K,N] + bias) ----------------
// 4 warps, warp tile (BM/2)x(BN/2). All operands pre-rounded to tf32 in gmem:
// mainloop = LDS + HMMA only, zero cvts.
template<int BM, int BN, int EPI>
__global__ void __launch_bounds__(128, 2) gemm_pipe(
    const float* __restrict__ A, const float* __restrict__ Bw,
    const float* __restrict__ bias, const float* __restrict__ Rres,
    float* __restrict__ C, int Mdim, int Ndim, int Kdim)
{
    constexpr int BK = 32;
    constexpr int STAGES = 3;
    constexpr int LDA = BK + 4;
    constexpr int LDB = BN + 4;
    constexpr int WTM = BM / 2;       // 64
    constexpr int WTN = BN / 2;       // 64 or 32
    constexpr int FM  = WTM / 16;     // 4
    constexpr int FN  = WTN / 16;     // 4 or 2
    constexpr int A_STG = BM * LDA;
    constexpr int B_STG = BK * LDB;

    extern __shared__ float sm[];
    float* As = sm;
    float* Bs = sm + STAGES * A_STG;

    const int tid = threadIdx.x;
    const int wid = tid >> 5;
    const int wm = wid >> 1, wn = wid & 1;
    const int bm0 = blockIdx.y * BM, bn0 = blockIdx.x * BN;

    wmma::fragment<wmma::accumulator, 16, 16, 8, float> acc[FM][FN];
#pragma unroll
    for (int i = 0; i < FM; i++)
#pragma unroll
        for (int j = 0; j < FN; j++) wmma::fill_fragment(acc[i][j], 0.0f);

    auto load_tile = [&](int stage, int k0) {
        float* Ad = As + stage * A_STG;
        float* Bd = Bs + stage * B_STG;
#pragma unroll
        for (int i = tid; i < BM * (BK / 4); i += 128) {
            int r = i >> 3, c = (i & 7) * 4;
            cp_async16(Ad + r * LDA + c, A + (size_t)(bm0 + r) * Kdim + k0 + c);
        }
#pragma unroll
        for (int i = tid; i < BK * (BN / 4); i += 128) {
            int r = i / (BN / 4), c = (i % (BN / 4)) * 4;
            cp_async16(Bd + r * LDB + c, Bw + (size_t)(k0 + r) * Ndim + bn0 + c);
        }
    };

    const int KT = Kdim / BK;
#pragma unroll
    for (int s = 0; s < STAGES - 1; ++s) {
        if (s < KT) load_tile(s, s * BK);
        cp_commit();
    }

    int read = 0, write = STAGES - 1;
    for (int it = 0; it < KT; ++it) {
        asm volatile("cp.async.wait_group %0;\n" :: "n"(STAGES - 2));
        __syncthreads();
        int knext = (it + STAGES - 1) * BK;
        if (knext < Kdim) load_tile(write, knext);
        cp_commit();

        const float* Asr = As + read * A_STG;
        const float* Bsr = Bs + read * B_STG;
#pragma unroll
        for (int kk = 0; kk < BK; kk += 8) {
            wmma::fragment<wmma::matrix_a, 16, 16, 8, wmma::precision::tf32, wmma::row_major> af[FM];
            wmma::fragment<wmma::matrix_b, 16, 16, 8, wmma::precision::tf32, wmma::row_major> bf[FN];
#pragma unroll
            for (int i = 0; i < FM; i++)
                wmma::load_matrix_sync(af[i], Asr + (wm * WTM + i * 16) * LDA + kk, LDA);
#pragma unroll
            for (int j = 0; j < FN; j++)
                wmma::load_matrix_sync(bf[j], Bsr + kk * LDB + wn * WTN + j * 16, LDB);
#pragma unroll
            for (int i = 0; i < FM; i++)
#pragma unroll
                for (int j = 0; j < FN; j++)
                    wmma::mma_sync(acc[i][j], af[i], bf[j], acc[i][j]);
        }
        read = (read + 1) % STAGES;
        write = (write + 1) % STAGES;
    }

    asm volatile("cp.async.wait_group 0;\n" ::);
    __syncthreads();

    float* Cs = sm;   // BM x LDB
#pragma unroll
    for (int i = 0; i < FM; i++)
#pragma unroll
        for (int j = 0; j < FN; j++)
            wmma::store_matrix_sync(Cs + (wm * WTM + i * 16) * LDB + wn * WTN + j * 16,
                                    acc[i][j], LDB, wmma::mem_row_major);
    __syncthreads();

#pragma unroll 4
    for (int i = tid; i < BM * (BN / 4); i += 128) {
        int r = i / (BN / 4), c = (i % (BN / 4)) * 4;
        float4 v = *(float4*)&Cs[r * LDB + c];
        float4 bb = *(const float4*)(bias + bn0 + c);
        v.x += bb.x; v.y += bb.y; v.z += bb.z; v.w += bb.w;
        if (EPI == EPI_GELU) {   // output feeds a GEMM A-operand -> round
            v.x = to_tf32(0.5f * v.x * (1.0f + erff(v.x * 0.70710678118654752f)));
            v.y = to_tf32(0.5f * v.y * (1.0f + erff(v.y * 0.70710678118654752f)));
            v.z = to_tf32(0.5f * v.z * (1.0f + erff(v.z * 0.70710678118654752f)));
            v.w = to_tf32(0.5f * v.w * (1.0f + erff(v.w * 0.70710678118654752f)));
        }
        if (EPI == EPI_RES) {
            float4 rr = *(const float4*)(Rres + (size_t)(bm0 + r) * Ndim + bn0 + c);
            v.x += rr.x; v.y += rr.y; v.z += rr.z; v.w += rr.w;
        }
        if (EPI == EPI_BIAS_RND) {
            v.x = to_tf32(v.x); v.y = to_tf32(v.y); v.z = to_tf32(v.z); v.w = to_tf32(v.w);
        }
        *(float4*)(C + (size_t)(bm0 + r) * Ndim + bn0 + c) = v;
    }
}

// ---------------- distance scores: P = tf32(exp(-g*dist)), rowl = row sums -----
__global__ void __launch_bounds__(256, 2) score_kernel(
    const float* __restrict__ zh, const float* __restrict__ gamma,
    float* __restrict__ P, float* __restrict__ rowl)
{
    __shared__ float zqs[64][17];
    __shared__ float zkt[16][132];
    __shared__ float ksq[128];

    const int b = blockIdx.z, h = blockIdx.y;
    const int q0 = blockIdx.x * 64;
    const int tid = threadIdx.x;
    const float gx = gamma[h];
    const float g = (gx > 20.f) ? gx : log1pf(__expf(gx));

    for (int i = tid; i < 64 * 4; i += 256) {
        int r = i >> 2, c = (i & 3) * 4;
        float4 v = *(const float4*)(zh + ((size_t)(b * S_ + q0 + r)) * (H_ * HC_) + h * HC_ + c);
        zqs[r][c] = v.x; zqs[r][c + 1] = v.y; zqs[r][c + 2] = v.z; zqs[r][c + 3] = v.w;
    }
    __syncthreads();

    const int qg = tid >> 4;
    const int kslot = tid & 15;
    float zq[4][16], qsq[4], l[4];
#pragma unroll
    for (int qi = 0; qi < 4; qi++) {
        float s = 0.f;
#pragma unroll
        for (int c = 0; c < 16; c++) { float v = zqs[qg * 4 + qi][c]; zq[qi][c] = v; s = fmaf(v, v, s); }
        qsq[qi] = s; l[qi] = 0.f;
    }

    const int bh = b * H_ + h;
    const size_t prow0 = ((size_t)bh * S_ + (q0 + qg * 4)) * S_;

    for (int k0 = 0; k0 < S_; k0 += 128) {
        __syncthreads();
        for (int i = tid; i < 128 * 4; i += 256) {
            int r = i >> 2, c = (i & 3) * 4;
            float4 v = *(const float4*)(zh + ((size_t)(b * S_ + k0 + r)) * (H_ * HC_) + h * HC_ + c);
            zkt[c][r] = v.x; zkt[c + 1][r] = v.y; zkt[c + 2][r] = v.z; zkt[c + 3][r] = v.w;
        }
        __syncthreads();
        if (tid < 128) {
            float s = 0.f;
#pragma unroll
            for (int c = 0; c < 16; c++) { float v = zkt[c][tid]; s = fmaf(v, v, s); }
            ksq[tid] = s;
        }
        __syncthreads();
#pragma unroll
        for (int j = 0; j < 8; j++) {
            int kk = j * 16 + kslot;
            float zk[16];
#pragma unroll
            for (int c = 0; c < 16; c++) zk[c] = zkt[c][kk];
            float kq = ksq[kk];
#pragma unroll
            for (int qi = 0; qi < 4; qi++) {
                float dot = 0.f;
#pragma unroll
                for (int c = 0; c < 16; c++) dot = fmaf(zq[qi][c], zk[c], dot);
                float d = fmaxf(qsq[qi] + kq - 2.f * dot, 0.f);
                float p = fast_exp_neg(-g * d);
                l[qi] += p;
                P[prow0 + (size_t)qi * S_ + k0 + kk] = to_tf32(p);
            }
        }
    }
#pragma unroll
    for (int off = 8; off > 0; off >>= 1) {
#pragma unroll
        for (int qi = 0; qi < 4; qi++)
            l[qi] += __shfl_xor_sync(0xffffffffu, l[qi], off);
    }
    if (kslot == 0) {
#pragma unroll
        for (int qi = 0; qi < 4; qi++)
            rowl[bh * S_ + q0 + qg * 4 + qi] = l[qi];
    }
}

// ---------------- PV: O = tf32((P @ V) * (1/rowl)), pipelined pure tf32 GEMM ----
__global__ void __launch_bounds__(256, 2) pv_pipe(
    const float* __restrict__ P, const float* __restrict__ rowl,
    const float* __restrict__ V, float* __restrict__ O)
{
    constexpr int BM = 128, BN = 64, BK = 32, STAGES = 3;
    constexpr int LDA = BK + 4, LDB = BN + 4;
    constexpr int A_STG = BM * LDA;
    constexpr int B_STG = BK * LDB;

    extern __shared__ float sm[];
    float* As = sm;
    float* Bs = sm + STAGES * A_STG;
    float* linv = sm + STAGES * (A_STG + B_STG);

    const int tid = threadIdx.x;
    const int wid = tid >> 5;
    const int bh = blockIdx.y;
    const int b = bh >> 4, h = bh & 15;
    const int q0 = blockIdx.x * BM;

    const float* Ab = P + (size_t)bh * S_ * S_;
    const float* Bb = V + (size_t)b * S_ * D_ + h * DH_;

    if (tid < BM) linv[tid] = 1.0f / rowl[bh * S_ + q0 + tid];

    wmma::fragment<wmma::accumulator, 16, 16, 8, float> acc[4];
#pragma unroll
    for (int j = 0; j < 4; j++) wmma::fill_fragment(acc[j], 0.0f);

    auto load_tile = [&](int stage, int k0) {
        float* Ad = As + stage * A_STG;
        float* Bd = Bs + stage * B_STG;
#pragma unroll
        for (int i = tid; i < BM * 8; i += 256) {
            int r = i >> 3, c = (i & 7) * 4;
            cp_async16(Ad + r * LDA + c, Ab + (size_t)(q0 + r) * S_ + k0 + c);
        }
#pragma unroll
        for (int i = tid; i < BK * 16; i += 256) {
            int r = i >> 4, c = (i & 15) * 4;
            cp_async16(Bd + r * LDB + c, Bb + (size_t)(k0 + r) * D_ + c);
        }
    };

    constexpr int KT = S_ / BK;
#pragma unroll
    for (int s = 0; s < STAGES - 1; ++s) {
        load_tile(s, s * BK);
        cp_commit();
    }

    int read = 0, write = STAGES - 1;
    for (int it = 0; it < KT; ++it) {
        asm volatile("cp.async.wait_group %0;\n" :: "n"(STAGES - 2));
        __syncthreads();
        int knext = (it + STAGES - 1) * BK;
        if (knext < S_) load_tile(write, knext);
        cp_commit();

        const float* Asr = As + read * A_STG;
        const float* Bsr = Bs + read * B_STG;
#pragma unroll
        for (int kk = 0; kk < BK; kk += 8) {
            wmma::fragment<wmma::matrix_a, 16, 16, 8, wmma::precision::tf32, wmma::row_major> af;
            wmma::load_matrix_sync(af, Asr + (wid * 16) * LDA + kk, LDA);
#pragma unroll
            for (int j = 0; j < 4; j++) {
                wmma::fragment<wmma::matrix_b, 16, 16, 8, wmma::precision::tf32, wmma::row_major> bf;
                wmma::load_matrix_sync(bf, Bsr + kk * LDB + j * 16, LDB);
                wmma::mma_sync(acc[j], af, bf, acc[j]);
            }
        }
        read = (read + 1) % STAGES;
        write = (write + 1) % STAGES;
    }

    asm volatile("cp.async.wait_group 0;\n" ::);
    __syncthreads();

    float* Cs = sm;
#pragma unroll
    for (int j = 0; j < 4; j++)
        wmma::store_matrix_sync(Cs + (wid * 16) * LDB + j * 16, acc[j], LDB, wmma::mem_row_major);
    __syncthreads();

#pragma unroll 4
    for (int i = tid; i < BM * 16; i += 256) {
        int r = i >> 4, c = (i & 15) * 4;
        float4 v = *(float4*)&Cs[r * LDB + c];
        float li = linv[r];
        v.x = to_tf32(v.x * li); v.y = to_tf32(v.y * li);
        v.z = to_tf32(v.z * li); v.w = to_tf32(v.w * li);
        *(float4*)(O + ((size_t)(b * S_ + q0 + r)) * D_ + h * DH_ + c) = v;
    }
}

// ---------------- LayerNorm over last dim (optionally tf32-rounded output) -----
__global__ void ln_kernel(const float* __restrict__ x, const float* __restrict__ gm,
                          const float* __restrict__ bt, float* __restrict__ y, int Dd, int rnd)
{
    const int row = blockIdx.x;
    const float* xr = x + (size_t)row * Dd;
    float s = 0.f, s2 = 0.f;
    for (int i = threadIdx.x; i < Dd; i += blockDim.x) {
        float v = xr[i]; s += v; s2 = fmaf(v, v, s2);
    }
    __shared__ float red[2][32];
    const int lane = threadIdx.x & 31, wid = threadIdx.x >> 5;
#pragma unroll
    for (int off = 16; off; off >>= 1) {
        s  += __shfl_xor_sync(0xffffffffu, s, off);
        s2 += __shfl_xor_sync(0xffffffffu, s2, off);
    }
    if (lane == 0) { red[0][wid] = s; red[1][wid] = s2; }
    __syncthreads();
    const int nw = blockDim.x >> 5;
    if (wid == 0) {
        s  = (lane < nw) ? red[0][lane] : 0.f;
        s2 = (lane < nw) ? red[1][lane] : 0.f;
#pragma unroll
        for (int off = 16; off; off >>= 1) {
            s  += __shfl_xor_sync(0xffffffffu, s, off);
            s2 += __shfl_xor_sync(0xffffffffu, s2, off);
        }
        if (lane == 0) { red[0][0] = s; red[1][0] = s2; }
    }
    __syncthreads();
    s = red[0][0]; s2 = red[1][0];
    const float mean = s / Dd;
    const float var  = s2 / Dd - mean * mean;
    const float inv  = rsqrtf(var + 1e-5f);
    float* yr = y + (size_t)row * Dd;
    if (rnd) {
        for (int i = threadIdx.x; i < Dd; i += blockDim.x)
            yr[i] = to_tf32((xr[i] - mean) * inv * gm[i] + bt[i]);
    } else {
        for (int i = threadIdx.x; i < Dd; i += blockDim.x)
            yr[i] = (xr[i] - mean) * inv * gm[i] + bt[i];
    }
}

// ---------------- launch ----------------
extern "C" void kernel_launch(void* const* d_in, const int* in_sizes, int n_in,
                              void* d_out, int out_size)
{
    const float* h    = (const float*)d_in[0];
    const float* z    = (const float*)d_in[1];
    const float* wv   = (const float*)d_in[2];
    const float* bv   = (const float*)d_in[3];
    const float* wca  = (const float*)d_in[4];
    const float* bca  = (const float*)d_in[5];
    const float* wcn  = (const float*)d_in[6];
    const float* bcn  = (const float*)d_in[7];
    const float* wo   = (const float*)d_in[8];
    const float* bo   = (const float*)d_in[9];
    const float* gamma= (const float*)d_in[10];
    const float* w1   = (const float*)d_in[11];
    const float* b1   = (const float*)d_in[12];
    const float* w2   = (const float*)d_in[13];
    const float* b2   = (const float*)d_in[14];
    const float* ln1g = (const float*)d_in[15];
    const float* ln1b = (const float*)d_in[16];
    const float* ln2g = (const float*)d_in[17];
    const float* ln2b = (const float*)d_in[18];
    const float* lncg = (const float*)d_in[19];
    const float* lncb = (const float*)d_in[20];

    float* out_h = (float*)d_out;
    float* out_z = out_h + (size_t)BS_ * D_;

    float *p_hn, *p_val, *p_zh, *p_P, *p_rl, *p_attn, *p_h1, *p_hn2, *p_mid, *p_ztmp;
    float *p_wv, *p_wca, *p_wcn, *p_wo, *p_w1, *p_w2, *p_z;
    cudaGetSymbolAddress((void**)&p_hn,  g_hn);
    cudaGetSymbolAddress((void**)&p_val, g_val);
    cudaGetSymbolAddress((void**)&p_zh,  g_zh);
    cudaGetSymbolAddress((void**)&p_P,   g_P);
    cudaGetSymbolAddress((void**)&p_rl,  g_rowl);
    cudaGetSymbolAddress((void**)&p_attn,g_attn);
    cudaGetSymbolAddress((void**)&p_h1,  g_h1);
    cudaGetSymbolAddress((void**)&p_hn2, g_hn2);
    cudaGetSymbolAddress((void**)&p_mid, g_mid);
    cudaGetSymbolAddress((void**)&p_ztmp,g_ztmp);
    cudaGetSymbolAddress((void**)&p_wv,  g_wv_r);
    cudaGetSymbolAddress((void**)&p_wca, g_wca_r);
    cudaGetSymbolAddress((void**)&p_wcn, g_wcn_r);
    cudaGetSymbolAddress((void**)&p_wo,  g_wo_r);
    cudaGetSymbolAddress((void**)&p_w1,  g_w1_r);
    cudaGetSymbolAddress((void**)&p_w2,  g_w2_r);
    cudaGetSymbolAddress((void**)&p_z,   g_z_r);

    constexpr int SM128 = 3 * (128 * 36 + 32 * 132) * 4;          // 105984 B
    constexpr int SM64  = 3 * (128 * 36 + 32 * 68) * 4;           //  81408 B
    constexpr int SMPV  = (3 * (128 * 36 + 32 * 68) + 128) * 4;   //  81920 B
    cudaFuncSetAttribute(gemm_pipe<128,128,EPI_BIAS>,     cudaFuncAttributeMaxDynamicSharedMemorySize, SM128);
    cudaFuncSetAttribute(gemm_pipe<128,128,EPI_BIAS_RND>, cudaFuncAttributeMaxDynamicSharedMemorySize, SM128);
    cudaFuncSetAttribute(gemm_pipe<128,128,EPI_RES >,     cudaFuncAttributeMaxDynamicSharedMemorySize, SM128);
    cudaFuncSetAttribute(gemm_pipe<128,128,EPI_GELU>,     cudaFuncAttributeMaxDynamicSharedMemorySize, SM128);
    cudaFuncSetAttribute(gemm_pipe<128, 64,EPI_RES >,     cudaFuncAttributeMaxDynamicSharedMemorySize, SM64);
    cudaFuncSetAttribute(pv_pipe,                         cudaFuncAttributeMaxDynamicSharedMemorySize, SMPV);

    // 0) round weights + z to tf32 (once per call; independent of everything below)
    auto rnd = [&](const float* src, float* dst, int n) {
        int n4 = n / 4;
        round_tf32_kernel<<<(n4 + 255) / 256, 256>>>(src, dst, n4);
    };
    rnd(wv,  p_wv,  D_*D_);
    rnd(wca, p_wca, DC_*H_*HC_);
    rnd(wcn, p_wcn, D_*DC_);
    rnd(wo,  p_wo,  D_*D_);
    rnd(w1,  p_w1,  D_*MFF_);
    rnd(w2,  p_w2,  MFF_*D_);
    rnd(z,   p_z,   BS_*DC_);

    // 1) hn = tf32(LN1(h))            (feeds GEMMs only)
    ln_kernel<<<BS_, 256>>>(h, ln1g, ln1b, p_hn, D_, 1);
    // 2) value = tf32(hn @ wv + bv)
    gemm_pipe<128,128,EPI_BIAS_RND><<<dim3(D_/128, BS_/128), 128, SM128>>>(p_hn, p_wv, bv, nullptr, p_val, BS_, D_, D_);
    // 3) zh = z_r @ wca + bca          (score input; fp32 out)
    gemm_pipe<128,128,EPI_BIAS><<<dim3(256/128, BS_/128), 128, SM128>>>(p_z, p_wca, bca, nullptr, p_zh, BS_, 256, DC_);
    // 4) z_tmp = z + (hn @ wcn + bcn)
    gemm_pipe<128,64,EPI_RES><<<dim3(1, BS_/128), 128, SM64>>>(p_hn, p_wcn, bcn, z, p_ztmp, BS_, DC_, D_);
    // 5) P = tf32(exp(-g*dist)), rowl = row sums
    score_kernel<<<dim3(S_/64, H_, B_), 256>>>(p_zh, gamma, p_P, p_rl);
    // 6) attn_out = tf32((P @ V) / rowl)
    pv_pipe<<<dim3(S_/128, BH_), 256, SMPV>>>(p_P, p_rl, p_val, p_attn);
    // 7) h1 = h + (attn_out @ wo + bo)
    gemm_pipe<128,128,EPI_RES><<<dim3(D_/128, BS_/128), 128, SM128>>>(p_attn, p_wo, bo, h, p_h1, BS_, D_, D_);
    // 8) hn2 = tf32(LN2(h1))
    ln_kernel<<<BS_, 256>>>(p_h1, ln2g, ln2b, p_hn2, D_, 1);
    // 9) mid = tf32(gelu(hn2 @ w1 + b1))
    gemm_pipe<128,128,EPI_GELU><<<dim3(MFF_/128, BS_/128), 128, SM128>>>(p_hn2, p_w1, b1, nullptr, p_mid, BS_, MFF_, D_);
    // 10) out_h = h1 + (mid @ w2 + b2)
    gemm_pipe<128,128,EPI_RES><<<dim3(D_/128, BS_/128), 128, SM128>>>(p_mid, p_w2, b2, p_h1, out_h, BS_, D_, MFF_);
    // 11) out_z = LN_c(z_tmp)          (final output; no rounding)
    ln_kernel<<<BS_, 64>>>(p_ztmp, lncg, lncb, out_z, DC_, 0);
}

// round 12
// speedup vs baseline: 3.2043x; 1.8679x over previous
#include <cuda_runtime.h>
#include <cuda_fp16.h>
#include <mma.h>
#include <math.h>

using namespace nvcuda;

#define B_   2
#define S_   2048
#define D_   1024
#define H_   16
#define DC_  64
#define HC_  16
#define MFF_ 4096
#define DH_  64
#define BS_  (B_*S_)      // 4096
#define BH_  (B_*H_)      // 32

// ---------------- scratch (static device globals; no allocation) ----------------
__device__ float  g_zh  [BS_*H_*HC_];
__device__ float  g_rowl[BH_*S_];
__device__ float  g_h1  [BS_*D_];
__device__ float  g_ztmp[BS_*DC_];
// half activations / operands
__device__ __half g_hn_h  [BS_*D_];
__device__ __half g_val_h [BS_*D_];
__device__ __half g_attn_h[BS_*D_];
__device__ __half g_hn2_h [BS_*D_];
__device__ __half g_mid_h [BS_*MFF_];
__device__ __half g_P_h   [134217728];   // B*H*S*S exp(logits), fp16
// half weight copies
__device__ __half g_wv_h [D_*D_];
__device__ __half g_wca_h[DC_*H_*HC_];
__device__ __half g_wcn_h[D_*DC_];
__device__ __half g_wo_h [D_*D_];
__device__ __half g_w1_h [D_*MFF_];
__device__ __half g_w2_h [MFF_*D_];
__device__ __half g_z_h  [BS_*DC_];

// exp(s) for s <= 0, FMA-pipe only (no MUFU). ~2.4e-6 max rel err.
__device__ __forceinline__ float fast_exp_neg(float s) {
    float y = fmaxf(s * 1.4426950408889634f, -126.0f);
    float z = y + 12582912.0f;
    float r = z - 12582912.0f;
    float f = y - r;
    int   iz = __float_as_int(z);
    float sc = __int_as_float((iz + (127 - 0x400000)) << 23);
    float p = 0.0013333558f;
    p = fmaf(p, f, 0.0096181291f);
    p = fmaf(p, f, 0.0555041087f);
    p = fmaf(p, f, 0.2402265070f);
    p = fmaf(p, f, 0.6931471806f);
    p = fmaf(p, f, 1.0f);
    return sc * p;
}

enum { EPI_BIAS_F32 = 0, EPI_RES_F32 = 1, EPI_GELU_H = 2, EPI_BIAS_H = 3 };

__device__ __forceinline__ void cp_async16(void* smem_dst, const void* gmem_src) {
    unsigned sa = (unsigned)__cvta_generic_to_shared(smem_dst);
    asm volatile("cp.async.cg.shared.global [%0], [%1], 16;\n" :: "r"(sa), "l"(gmem_src));
}
__device__ __forceinline__ void cp_commit() {
    asm volatile("cp.async.commit_group;\n" ::);
}

// ---------------- fp32 -> fp16 conversion (float4 -> 4 halves) ----------------
__global__ void f2h_kernel(const float* __restrict__ x, __half* __restrict__ y, int n4) {
    int i = blockIdx.x * blockDim.x + threadIdx.x;
    if (i < n4) {
        float4 v = ((const float4*)x)[i];
        __half2* yp = (__half2*)y;
        yp[2*i]   = __floats2half2_rn(v.x, v.y);
        yp[2*i+1] = __floats2half2_rn(v.z, v.w);
    }
}

// ---------------- pipelined fp16 GEMM: C = epi(A[M,K] @ B[K,N] + bias) ----------------
// fp16 operands (11-bit mantissa == tf32), fp32 accumulate. 3-stage cp.async.
// 4 warps, warp tile (BM/2)x(BN/2), k16 HMMA steps.
template<int BM, int BN, int EPI>
__global__ void __launch_bounds__(128, 2) gemm_h(
    const __half* __restrict__ A, const __half* __restrict__ Bw,
    const float* __restrict__ bias, const float* __restrict__ Rres,
    void* __restrict__ Cout, int Mdim, int Ndim, int Kdim)
{
    constexpr int BK = 32;
    constexpr int STAGES = 3;
    constexpr int LDA = BK + 8;       // halves; 80B rows, 16B aligned
    constexpr int LDB = BN + 8;       // 136 or 72
    constexpr int LDC = BN + 4;       // fp32 C tile
    constexpr int WTM = BM / 2;       // 64
    constexpr int WTN = BN / 2;       // 64 or 32
    constexpr int FM  = WTM / 16;     // 4
    constexpr int FN  = WTN / 16;     // 4 or 2
    constexpr int A_STG = BM * LDA;
    constexpr int B_STG = BK * LDB;
    constexpr int CHB = BN / 8;       // 8-half chunks per B row

    extern __shared__ __align__(16) char smraw[];
    __half* As = (__half*)smraw;
    __half* Bs = As + STAGES * A_STG;

    const int tid = threadIdx.x;
    const int wid = tid >> 5;
    const int wm = wid >> 1, wn = wid & 1;
    const int bm0 = blockIdx.y * BM, bn0 = blockIdx.x * BN;

    wmma::fragment<wmma::accumulator, 16, 16, 16, float> acc[FM][FN];
#pragma unroll
    for (int i = 0; i < FM; i++)
#pragma unroll
        for (int j = 0; j < FN; j++) wmma::fill_fragment(acc[i][j], 0.0f);

    auto load_tile = [&](int stage, int k0) {
        __half* Ad = As + stage * A_STG;
        __half* Bd = Bs + stage * B_STG;
#pragma unroll
        for (int i = tid; i < BM * 4; i += 128) {         // BK/8 = 4 chunks per A row
            int r = i >> 2, c = (i & 3) * 8;
            cp_async16(Ad + r * LDA + c, A + (size_t)(bm0 + r) * Kdim + k0 + c);
        }
#pragma unroll
        for (int i = tid; i < BK * CHB; i += 128) {
            int r = i / CHB, c = (i % CHB) * 8;
            cp_async16(Bd + r * LDB + c, Bw + (size_t)(k0 + r) * Ndim + bn0 + c);
        }
    };

    const int KT = Kdim / BK;
#pragma unroll
    for (int s = 0; s < STAGES - 1; ++s) {
        if (s < KT) load_tile(s, s * BK);
        cp_commit();
    }

    int read = 0, write = STAGES - 1;
    for (int it = 0; it < KT; ++it) {
        asm volatile("cp.async.wait_group %0;\n" :: "n"(STAGES - 2));
        __syncthreads();
        int knext = (it + STAGES - 1) * BK;
        if (knext < Kdim) load_tile(write, knext);
        cp_commit();

        const __half* Asr = As + read * A_STG;
        const __half* Bsr = Bs + read * B_STG;
#pragma unroll
        for (int kk = 0; kk < BK; kk += 16) {
            wmma::fragment<wmma::matrix_a, 16, 16, 16, __half, wmma::row_major> af[FM];
            wmma::fragment<wmma::matrix_b, 16, 16, 16, __half, wmma::row_major> bf[FN];
#pragma unroll
            for (int i = 0; i < FM; i++)
                wmma::load_matrix_sync(af[i], Asr + (wm * WTM + i * 16) * LDA + kk, LDA);
#pragma unroll
            for (int j = 0; j < FN; j++)
                wmma::load_matrix_sync(bf[j], Bsr + kk * LDB + wn * WTN + j * 16, LDB);
#pragma unroll
            for (int i = 0; i < FM; i++)
#pragma unroll
                for (int j = 0; j < FN; j++)
                    wmma::mma_sync(acc[i][j], af[i], bf[j], acc[i][j]);
        }
        read = (read + 1) % STAGES;
        write = (write + 1) % STAGES;
    }

    asm volatile("cp.async.wait_group 0;\n" ::);
    __syncthreads();

    float* Cs = (float*)smraw;   // BM x LDC fp32 (overlays stage buffers)
#pragma unroll
    for (int i = 0; i < FM; i++)
#pragma unroll
        for (int j = 0; j < FN; j++)
            wmma::store_matrix_sync(Cs + (wm * WTM + i * 16) * LDC + wn * WTN + j * 16,
                                    acc[i][j], LDC, wmma::mem_row_major);
    __syncthreads();

#pragma unroll 4
    for (int i = tid; i < BM * (BN / 4); i += 128) {
        int r = i / (BN / 4), c = (i % (BN / 4)) * 4;
        float4 v = *(float4*)&Cs[r * LDC + c];
        float4 bb = *(const float4*)(bias + bn0 + c);
        v.x += bb.x; v.y += bb.y; v.z += bb.z; v.w += bb.w;
        size_t off = (size_t)(bm0 + r) * Ndim + bn0 + c;
        if (EPI == EPI_BIAS_F32) {
            *(float4*)((float*)Cout + off) = v;
        } else if (EPI == EPI_RES_F32) {
            float4 rr = *(const float4*)(Rres + off);
            v.x += rr.x; v.y += rr.y; v.z += rr.z; v.w += rr.w;
            *(float4*)((float*)Cout + off) = v;
        } else if (EPI == EPI_GELU_H) {
            v.x = 0.5f * v.x * (1.0f + erff(v.x * 0.70710678118654752f));
            v.y = 0.5f * v.y * (1.0f + erff(v.y * 0.70710678118654752f));
            v.z = 0.5f * v.z * (1.0f + erff(v.z * 0.70710678118654752f));
            v.w = 0.5f * v.w * (1.0f + erff(v.w * 0.70710678118654752f));
            __half2* yp = (__half2*)((__half*)Cout + off);
            yp[0] = __floats2half2_rn(v.x, v.y);
            yp[1] = __floats2half2_rn(v.z, v.w);
        } else {  // EPI_BIAS_H
            __half2* yp = (__half2*)((__half*)Cout + off);
            yp[0] = __floats2half2_rn(v.x, v.y);
            yp[1] = __floats2half2_rn(v.z, v.w);
        }
    }
}

// ---------------- distance scores: P = fp16(exp(-g*dist)), rowl = row sums -----
// Row max is exactly 0 (diagonal distance = 0) -> exp(s) directly; p in [0,1].
__global__ void __launch_bounds__(256, 2) score_kernel(
    const float* __restrict__ zh, const float* __restrict__ gamma,
    __half* __restrict__ P, float* __restrict__ rowl)
{
    __shared__ float zqs[64][17];
    __shared__ float zkt[16][132];
    __shared__ float ksq[128];

    const int b = blockIdx.z, h = blockIdx.y;
    const int q0 = blockIdx.x * 64;
    const int tid = threadIdx.x;
    const float gx = gamma[h];
    const float g = (gx > 20.f) ? gx : log1pf(__expf(gx));

    for (int i = tid; i < 64 * 4; i += 256) {
        int r = i >> 2, c = (i & 3) * 4;
        float4 v = *(const float4*)(zh + ((size_t)(b * S_ + q0 + r)) * (H_ * HC_) + h * HC_ + c);
        zqs[r][c] = v.x; zqs[r][c + 1] = v.y; zqs[r][c + 2] = v.z; zqs[r][c + 3] = v.w;
    }
    __syncthreads();

    const int qg = tid >> 4;
    const int kslot = tid & 15;
    float zq[4][16], qsq[4], l[4];
#pragma unroll
    for (int qi = 0; qi < 4; qi++) {
        float s = 0.f;
#pragma unroll
        for (int c = 0; c < 16; c++) { float v = zqs[qg * 4 + qi][c]; zq[qi][c] = v; s = fmaf(v, v, s); }
        qsq[qi] = s; l[qi] = 0.f;
    }

    const int bh = b * H_ + h;
    const size_t prow0 = ((size_t)bh * S_ + (q0 + qg * 4)) * S_;

    for (int k0 = 0; k0 < S_; k0 += 128) {
        __syncthreads();
        for (int i = tid; i < 128 * 4; i += 256) {
            int r = i >> 2, c = (i & 3) * 4;
            float4 v = *(const float4*)(zh + ((size_t)(b * S_ + k0 + r)) * (H_ * HC_) + h * HC_ + c);
            zkt[c][r] = v.x; zkt[c + 1][r] = v.y; zkt[c + 2][r] = v.z; zkt[c + 3][r] = v.w;
        }
        __syncthreads();
        if (tid < 128) {
            float s = 0.f;
#pragma unroll
            for (int c = 0; c < 16; c++) { float v = zkt[c][tid]; s = fmaf(v, v, s); }
            ksq[tid] = s;
        }
        __syncthreads();
#pragma unroll
        for (int j = 0; j < 8; j++) {
            int kk = j * 16 + kslot;
            float zk[16];
#pragma unroll
            for (int c = 0; c < 16; c++) zk[c] = zkt[c][kk];
            float kq = ksq[kk];
#pragma unroll
            for (int qi = 0; qi < 4; qi++) {
                float dot = 0.f;
#pragma unroll
                for (int c = 0; c < 16; c++) dot = fmaf(zq[qi][c], zk[c], dot);
                float d = fmaxf(qsq[qi] + kq - 2.f * dot, 0.f);
                float p = fast_exp_neg(-g * d);
                l[qi] += p;
                P[prow0 + (size_t)qi * S_ + k0 + kk] = __float2half_rn(p);
            }
        }
    }
#pragma unroll
    for (int off = 8; off > 0; off >>= 1) {
#pragma unroll
        for (int qi = 0; qi < 4; qi++)
            l[qi] += __shfl_xor_sync(0xffffffffu, l[qi], off);
    }
    if (kslot == 0) {
#pragma unroll
        for (int qi = 0; qi < 4; qi++)
            rowl[bh * S_ + q0 + qg * 4 + qi] = l[qi];
    }
}

// ---------------- PV: attn = fp16((P @ V) / rowl), fp16 HMMA pipelined GEMM ----
__global__ void __launch_bounds__(256, 2) pv_pipe(
    const __half* __restrict__ P, const float* __restrict__ rowl,
    const __half* __restrict__ V, __half* __restrict__ O)
{
    constexpr int BM = 128, BN = 64, BK = 32, STAGES = 3;
    constexpr int LDA = BK + 8;   // 40 halves
    constexpr int LDB = BN + 8;   // 72
    constexpr int LDC = BN + 4;   // 68 fp32
    constexpr int A_STG = BM * LDA;   // 5120
    constexpr int B_STG = BK * LDB;   // 2304

    extern __shared__ __align__(16) char smraw[];
    __half* As = (__half*)smraw;
    __half* Bs = As + STAGES * A_STG;
    float* linv = (float*)(smraw + STAGES * (A_STG + B_STG) * 2);   // 44544B offset

    const int tid = threadIdx.x;
    const int wid = tid >> 5;
    const int bh = blockIdx.y;
    const int b = bh >> 4, h = bh & 15;
    const int q0 = blockIdx.x * BM;

    const __half* Ab = P + (size_t)bh * S_ * S_;
    const __half* Bb = V + (size_t)b * S_ * D_ + h * DH_;

    if (tid < BM) linv[tid] = 1.0f / rowl[bh * S_ + q0 + tid];

    wmma::fragment<wmma::accumulator, 16, 16, 16, float> acc[4];
#pragma unroll
    for (int j = 0; j < 4; j++) wmma::fill_fragment(acc[j], 0.0f);

    auto load_tile = [&](int stage, int k0) {
        __half* Ad = As + stage * A_STG;
        __half* Bd = Bs + stage * B_STG;
#pragma unroll
        for (int i = tid; i < BM * 4; i += 256) {
            int r = i >> 2, c = (i & 3) * 8;
            cp_async16(Ad + r * LDA + c, Ab + (size_t)(q0 + r) * S_ + k0 + c);
        }
#pragma unroll
        for (int i = tid; i < BK * 8; i += 256) {
            int r = i >> 3, c = (i & 7) * 8;
            cp_async16(Bd + r * LDB + c, Bb + (size_t)(k0 + r) * D_ + c);
        }
    };

    constexpr int KT = S_ / BK;
#pragma unroll
    for (int s = 0; s < STAGES - 1; ++s) {
        load_tile(s, s * BK);
        cp_commit();
    }

    int read = 0, write = STAGES - 1;
    for (int it = 0; it < KT; ++it) {
        asm volatile("cp.async.wait_group %0;\n" :: "n"(STAGES - 2));
        __syncthreads();
        int knext = (it + STAGES - 1) * BK;
        if (knext < S_) load_tile(write, knext);
        cp_commit();

        const __half* Asr = As + read * A_STG;
        const __half* Bsr = Bs + read * B_STG;
#pragma unroll
        for (int kk = 0; kk < BK; kk += 16) {
            wmma::fragment<wmma::matrix_a, 16, 16, 16, __half, wmma::row_major> af;
            wmma::load_matrix_sync(af, Asr + (wid * 16) * LDA + kk, LDA);
#pragma unroll
            for (int j = 0; j < 4; j++) {
                wmma::fragment<wmma::matrix_b, 16, 16, 16, __half, wmma::row_major> bf;
                wmma::load_matrix_sync(bf, Bsr + kk * LDB + j * 16, LDB);
                wmma::mma_sync(acc[j], af, bf, acc[j]);
            }
        }
        read = (read + 1) % STAGES;
        write = (write + 1) % STAGES;
    }

    asm volatile("cp.async.wait_group 0;\n" ::);
    __syncthreads();

    float* Cs = (float*)smraw;   // 128 x 68 fp32 (34816B < linv offset)
#pragma unroll
    for (int j = 0; j < 4; j++)
        wmma::store_matrix_sync(Cs + (wid * 16) * LDC + j * 16, acc[j], LDC, wmma::mem_row_major);
    __syncthreads();

#pragma unroll 4
    for (int i = tid; i < BM * 16; i += 256) {
        int r = i >> 4, c = (i & 15) * 4;
        float4 v = *(float4*)&Cs[r * LDC + c];
        float li = linv[r];
        v.x *= li; v.y *= li; v.z *= li; v.w *= li;
        __half2* yp = (__half2*)(O + ((size_t)(b * S_ + q0 + r)) * D_ + h * DH_ + c);
        yp[0] = __floats2half2_rn(v.x, v.y);
        yp[1] = __floats2half2_rn(v.z, v.w);
    }
}

// ---------------- LayerNorm over last dim (fp32 or fp16 output) ----------------
template<bool HOUT>
__global__ void ln_kernel(const float* __restrict__ x, const float* __restrict__ gm,
                          const float* __restrict__ bt, void* __restrict__ y, int Dd)
{
    const int row = blockIdx.x;
    const float* xr = x + (size_t)row * Dd;
    float s = 0.f, s2 = 0.f;
    for (int i = threadIdx.x; i < Dd; i += blockDim.x) {
        float v = xr[i]; s += v; s2 = fmaf(v, v, s2);
    }
    __shared__ float red[2][32];
    const int lane = threadIdx.x & 31, wid = threadIdx.x >> 5;
#pragma unroll
    for (int off = 16; off; off >>= 1) {
        s  += __shfl_xor_sync(0xffffffffu, s, off);
        s2 += __shfl_xor_sync(0xffffffffu, s2, off);
    }
    if (lane == 0) { red[0][wid] = s; red[1][wid] = s2; }
    __syncthreads();
    const int nw = blockDim.x >> 5;
    if (wid == 0) {
        s  = (lane < nw) ? red[0][lane] : 0.f;
        s2 = (lane < nw) ? red[1][lane] : 0.f;
#pragma unroll
        for (int off = 16; off; off >>= 1) {
            s  += __shfl_xor_sync(0xffffffffu, s, off);
            s2 += __shfl_xor_sync(0xffffffffu, s2, off);
        }
        if (lane == 0) { red[0][0] = s; red[1][0] = s2; }
    }
    __syncthreads();
    s = red[0][0]; s2 = red[1][0];
    const float mean = s / Dd;
    const float var  = s2 / Dd - mean * mean;
    const float inv  = rsqrtf(var + 1e-5f);
    for (int i = threadIdx.x; i < Dd; i += blockDim.x) {
        float o = (xr[i] - mean) * inv * gm[i] + bt[i];
        if (HOUT) ((__half*)y)[(size_t)row * Dd + i] = __float2half_rn(o);
        else      ((float*)y)[(size_t)row * Dd + i] = o;
    }
}

// ---------------- launch ----------------
extern "C" void kernel_launch(void* const* d_in, const int* in_sizes, int n_in,
                              void* d_out, int out_size)
{
    const float* h    = (const float*)d_in[0];
    const float* z    = (const float*)d_in[1];
    const float* wv   = (const float*)d_in[2];
    const float* bv   = (const float*)d_in[3];
    const float* wca  = (const float*)d_in[4];
    const float* bca  = (const float*)d_in[5];
    const float* wcn  = (const float*)d_in[6];
    const float* bcn  = (const float*)d_in[7];
    const float* wo   = (const float*)d_in[8];
    const float* bo   = (const float*)d_in[9];
    const float* gamma= (const float*)d_in[10];
    const float* w1   = (const float*)d_in[11];
    const float* b1   = (const float*)d_in[12];
    const float* w2   = (const float*)d_in[13];
    const float* b2   = (const float*)d_in[14];
    const float* ln1g = (const float*)d_in[15];
    const float* ln1b = (const float*)d_in[16];
    const float* ln2g = (const float*)d_in[17];
    const float* ln2b = (const float*)d_in[18];
    const float* lncg = (const float*)d_in[19];
    const float* lncb = (const float*)d_in[20];

    float* out_h = (float*)d_out;
    float* out_z = out_h + (size_t)BS_ * D_;

    float  *p_zh, *p_rl, *p_h1, *p_ztmp;
    __half *p_hn, *p_val, *p_attn, *p_hn2, *p_mid, *p_P;
    __half *p_wv, *p_wca, *p_wcn, *p_wo, *p_w1, *p_w2, *p_z;
    cudaGetSymbolAddress((void**)&p_zh,  g_zh);
    cudaGetSymbolAddress((void**)&p_rl,  g_rowl);
    cudaGetSymbolAddress((void**)&p_h1,  g_h1);
    cudaGetSymbolAddress((void**)&p_ztmp,g_ztmp);
    cudaGetSymbolAddress((void**)&p_hn,  g_hn_h);
    cudaGetSymbolAddress((void**)&p_val, g_val_h);
    cudaGetSymbolAddress((void**)&p_attn,g_attn_h);
    cudaGetSymbolAddress((void**)&p_hn2, g_hn2_h);
    cudaGetSymbolAddress((void**)&p_mid, g_mid_h);
    cudaGetSymbolAddress((void**)&p_P,   g_P_h);
    cudaGetSymbolAddress((void**)&p_wv,  g_wv_h);
    cudaGetSymbolAddress((void**)&p_wca, g_wca_h);
    cudaGetSymbolAddress((void**)&p_wcn, g_wcn_h);
    cudaGetSymbolAddress((void**)&p_wo,  g_wo_h);
    cudaGetSymbolAddress((void**)&p_w1,  g_w1_h);
    cudaGetSymbolAddress((void**)&p_w2,  g_w2_h);
    cudaGetSymbolAddress((void**)&p_z,   g_z_h);

    // dynamic smem: stages (half) vs fp32 C-tile, take max
    constexpr int SM128 = ((3 * (128*40 + 32*136) * 2) > (128*132*4)) ? (3 * (128*40 + 32*136) * 2) : (128*132*4);  // 67584
    constexpr int SM64  = 3 * (128*40 + 32*72) * 2;                  // 44544 (> C 34816)
    constexpr int SMPV  = 3 * (128*40 + 32*72) * 2 + 512;            // stages + linv
    cudaFuncSetAttribute(gemm_h<128,128,EPI_BIAS_F32>, cudaFuncAttributeMaxDynamicSharedMemorySize, SM128);
    cudaFuncSetAttribute(gemm_h<128,128,EPI_RES_F32 >, cudaFuncAttributeMaxDynamicSharedMemorySize, SM128);
    cudaFuncSetAttribute(gemm_h<128,128,EPI_GELU_H  >, cudaFuncAttributeMaxDynamicSharedMemorySize, SM128);
    cudaFuncSetAttribute(gemm_h<128,128,EPI_BIAS_H  >, cudaFuncAttributeMaxDynamicSharedMemorySize, SM128);
    cudaFuncSetAttribute(gemm_h<128, 64,EPI_RES_F32 >, cudaFuncAttributeMaxDynamicSharedMemorySize, SM64);
    cudaFuncSetAttribute(pv_pipe,                      cudaFuncAttributeMaxDynamicSharedMemorySize, SMPV);

    auto cvt = [&](const float* src, __half* dst, int n) {
        int n4 = n / 4;
        f2h_kernel<<<(n4 + 255) / 256, 256>>>(src, dst, n4);
    };

    // Launch order puts the value GEMM at slot 5 (ncu -s 5 -c 1 captures it).
    cvt(wv,  p_wv,  D_*D_);                                                         // 0
    cvt(z,   p_z,   BS_*DC_);                                                       // 1
    cvt(wca, p_wca, DC_*H_*HC_);                                                    // 2
    ln_kernel<true><<<BS_, 256>>>(h, ln1g, ln1b, p_hn, D_);                         // 3
    gemm_h<128,128,EPI_BIAS_F32><<<dim3(2, BS_/128), 128, SM128>>>(p_z, p_wca, bca, nullptr, p_zh, BS_, 256, DC_);          // 4
    gemm_h<128,128,EPI_BIAS_H><<<dim3(D_/128, BS_/128), 128, SM128>>>(p_hn, p_wv, bv, nullptr, p_val, BS_, D_, D_);         // 5 (profiled)
    cvt(wcn, p_wcn, D_*DC_);                                                        // 6
    cvt(wo,  p_wo,  D_*D_);
    cvt(w1,  p_w1,  D_*MFF_);
    cvt(w2,  p_w2,  MFF_*D_);
    // z_tmp = z + (hn @ wcn + bcn)
    gemm_h<128,64,EPI_RES_F32><<<dim3(1, BS_/128), 128, SM64>>>(p_hn, p_wcn, bcn, z, p_ztmp, BS_, DC_, D_);
    // P = fp16(exp(-g*dist)), rowl = row sums
    score_kernel<<<dim3(S_/64, H_, B_), 256>>>(p_zh, gamma, p_P, p_rl);
    // attn = fp16((P @ V) / rowl)
    pv_pipe<<<dim3(S_/128, BH_), 256, SMPV>>>(p_P, p_rl, p_val, p_attn);
    // h1 = h + (attn @ wo + bo)
    gemm_h<128,128,EPI_RES_F32><<<dim3(D_/128, BS_/128), 128, SM128>>>(p_attn, p_wo, bo, h, p_h1, BS_, D_, D_);
    // hn2 = fp16(LN2(h1))
    ln_kernel<true><<<BS_, 256>>>(p_h1, ln2g, ln2b, p_hn2, D_);
    // mid = fp16(gelu(hn2 @ w1 + b1))
    gemm_h<128,128,EPI_GELU_H><<<dim3(MFF_/128, BS_/128), 128, SM128>>>(p_hn2, p_w1, b1, nullptr, p_mid, BS_, MFF_, D_);
    // out_h = h1 + (mid @ w2 + b2)
    gemm_h<128,128,EPI_RES_F32><<<dim3(D_/128, BS_/128), 128, SM128>>>(p_mid, p_w2, b2, p_h1, out_h, BS_, D_, MFF_);
    // out_z = LN_c(z_tmp)  (final output, fp32)
    ln_kernel<false><<<BS_, 64>>>(p_ztmp, lncg, lncb, out_z, DC_);
}

// round 13
// speedup vs baseline: 5.1526x; 1.6080x over previous
#include <cuda_runtime.h>
#include <cuda_fp16.h>
#include <mma.h>
#include <math.h>

using namespace nvcuda;

#define B_   2
#define S_   2048
#define D_   1024
#define H_   16
#define DC_  64
#define HC_  16
#define MFF_ 4096
#define DH_  64
#define BS_  (B_*S_)      // 4096
#define BH_  (B_*H_)      // 32

// ---------------- scratch (static device globals; no allocation) ----------------
__device__ float  g_zh  [BS_*H_*HC_];
__device__ float  g_rowl[BH_*S_];
__device__ float  g_h1  [BS_*D_];
__device__ float  g_ztmp[BS_*DC_];
__device__ float  g_zsq [BS_*H_];
// half activations / operands
__device__ __half g_hn_h  [BS_*D_];
__device__ __half g_val_h [BS_*D_];
__device__ __half g_attn_h[BS_*D_];
__device__ __half g_hn2_h [BS_*D_];
__device__ __half g_mid_h [BS_*MFF_];
__device__ __half g_P_h   [134217728];   // B*H*S*S exp(logits), fp16
__device__ __half g_zhi   [BS_*H_*HC_];  // hi part of zh (Dekker split)
__device__ __half g_zlo   [BS_*H_*HC_];  // lo part
// half weight copies
__device__ __half g_wv_h [D_*D_];
__device__ __half g_wca_h[DC_*H_*HC_];
__device__ __half g_wcn_h[D_*DC_];
__device__ __half g_wo_h [D_*D_];
__device__ __half g_w1_h [D_*MFF_];
__device__ __half g_w2_h [MFF_*D_];
__device__ __half g_z_h  [BS_*DC_];

// exp(s) for s <= 0, FMA-pipe only (no MUFU). ~2.4e-6 max rel err.
__device__ __forceinline__ float fast_exp_neg(float s) {
    float y = fmaxf(s * 1.4426950408889634f, -126.0f);
    float z = y + 12582912.0f;
    float r = z - 12582912.0f;
    float f = y - r;
    int   iz = __float_as_int(z);
    float sc = __int_as_float((iz + (127 - 0x400000)) << 23);
    float p = 0.0013333558f;
    p = fmaf(p, f, 0.0096181291f);
    p = fmaf(p, f, 0.0555041087f);
    p = fmaf(p, f, 0.2402265070f);
    p = fmaf(p, f, 0.6931471806f);
    p = fmaf(p, f, 1.0f);
    return sc * p;
}

enum { EPI_BIAS_F32 = 0, EPI_RES_F32 = 1, EPI_GELU_H = 2, EPI_BIAS_H = 3 };

__device__ __forceinline__ void cp_async16(void* smem_dst, const void* gmem_src) {
    unsigned sa = (unsigned)__cvta_generic_to_shared(smem_dst);
    asm volatile("cp.async.cg.shared.global [%0], [%1], 16;\n" :: "r"(sa), "l"(gmem_src));
}
__device__ __forceinline__ void cp_commit() {
    asm volatile("cp.async.commit_group;\n" ::);
}

// ---------------- fp32 -> fp16 conversion (float4 -> 4 halves) ----------------
__global__ void f2h_kernel(const float* __restrict__ x, __half* __restrict__ y, int n4) {
    int i = blockIdx.x * blockDim.x + threadIdx.x;
    if (i < n4) {
        float4 v = ((const float4*)x)[i];
        __half2* yp = (__half2*)y;
        yp[2*i]   = __floats2half2_rn(v.x, v.y);
        yp[2*i+1] = __floats2half2_rn(v.z, v.w);
    }
}

// ---------------- score prep: Dekker split zh -> (hi, lo) fp16 + per-head norms --
// thread t handles one (row, head): 16 contiguous floats.
__global__ void score_prep(const float* __restrict__ zh, __half* __restrict__ hi,
                           __half* __restrict__ lo, float* __restrict__ zsq)
{
    int t = blockIdx.x * blockDim.x + threadIdx.x;
    if (t >= BS_ * H_) return;
    const float4* src = (const float4*)(zh + (size_t)t * 16);
    __half hb[16], lb[16];
    float s = 0.f;
#pragma unroll
    for (int q = 0; q < 4; q++) {
        float4 v = src[q];
        float vv[4] = {v.x, v.y, v.z, v.w};
#pragma unroll
        for (int j = 0; j < 4; j++) {
            float x = vv[j];
            __half hx = __float2half_rn(x);
            float  rx = x - __half2float(hx);
            hb[q*4+j] = hx;
            lb[q*4+j] = __float2half_rn(rx);
            s = fmaf(x, x, s);
        }
    }
    ((uint4*)(hi + (size_t)t * 16))[0] = ((uint4*)hb)[0];
    ((uint4*)(hi + (size_t)t * 16))[1] = ((uint4*)hb)[1];
    ((uint4*)(lo + (size_t)t * 16))[0] = ((uint4*)lb)[0];
    ((uint4*)(lo + (size_t)t * 16))[1] = ((uint4*)lb)[1];
    zsq[t] = s;
}

// ---------------- tensor-core score: P = fp16(exp(-g*dist)), rowl = rowsums ----
// CTA: 128 q-rows for one (b,h); loops 16 k-tiles of 128.
// dot via 3 HMMAs (hi*hi + hi*lo + lo*hi) -> fp32-accurate (Dekker).
// smem layout (bytes):
//  qh 0..6144, ql 6144..12288, kh 12288..18432, kl 18432..24576,
//  qsq 24576..25088, ksq 25088..25600, C 25600..60416 (128x68 fp32)
#define SC_QH  0
#define SC_QL  6144
#define SC_KH  12288
#define SC_KL  18432
#define SC_QSQ 24576
#define SC_KSQ 25088
#define SC_C   25600
#define SC_SMEM 60416

__global__ void __launch_bounds__(256, 2) score_mma(
    const __half* __restrict__ zhi, const __half* __restrict__ zlo,
    const float* __restrict__ zsq, const float* __restrict__ gamma,
    __half* __restrict__ P, float* __restrict__ rowl)
{
    constexpr int LDQ = 24;   // halves
    constexpr int LDC = 68;   // floats
    extern __shared__ __align__(16) char smraw[];
    __half* qh  = (__half*)(smraw + SC_QH);
    __half* ql  = (__half*)(smraw + SC_QL);
    __half* kh  = (__half*)(smraw + SC_KH);
    __half* kl  = (__half*)(smraw + SC_KL);
    float*  qsq = (float*)(smraw + SC_QSQ);
    float*  ksq = (float*)(smraw + SC_KSQ);
    float*  C   = (float*)(smraw + SC_C);

    const int tid = threadIdx.x;
    const int wid = tid >> 5;
    const int bh = blockIdx.y;
    const int b = bh >> 4, h = bh & 15;
    const int q0 = blockIdx.x * 128;

    const float gx = gamma[h];
    const float g = (gx > 20.f) ? gx : log1pf(__expf(gx));

    // load q tiles: 128 rows x 16 halves (hi & lo) + norms
    {
        int r = tid >> 1, part = tid & 1;
        size_t go = ((size_t)(b * S_ + q0 + r)) * (H_ * HC_) + h * 16 + part * 8;
        *(uint4*)(qh + r * LDQ + part * 8) = *(const uint4*)(zhi + go);
        *(uint4*)(ql + r * LDQ + part * 8) = *(const uint4*)(zlo + go);
        if (part == 0) qsq[r] = zsq[(size_t)(b * S_ + q0 + r) * H_ + h];
    }
    __syncthreads();

    // A fragments (constant over k loop)
    wmma::fragment<wmma::matrix_a, 16, 16, 16, __half, wmma::row_major> a_hi, a_lo;
    wmma::load_matrix_sync(a_hi, qh + (wid * 16) * LDQ, LDQ);
    wmma::load_matrix_sync(a_lo, ql + (wid * 16) * LDQ, LDQ);

    const int row = tid >> 1;
    const int c0  = (tid & 1) * 32;
    const float qs = qsq[row];
    float rs = 0.f;

    for (int kt = 0; kt < 16; ++kt) {
        const int k0 = kt * 128;
        __syncthreads();   // previous epilogue done with kh/ksq/C
        {
            int r = tid >> 1, part = tid & 1;
            size_t go = ((size_t)(b * S_ + k0 + r)) * (H_ * HC_) + h * 16 + part * 8;
            *(uint4*)(kh + r * LDQ + part * 8) = *(const uint4*)(zhi + go);
            *(uint4*)(kl + r * LDQ + part * 8) = *(const uint4*)(zlo + go);
            if (part == 0) ksq[r] = zsq[(size_t)(b * S_ + k0 + r) * H_ + h];
        }
        __syncthreads();

        // MMA: warp wid owns q rows wid*16..+15, all 128 key cols (8 frags)
        wmma::fragment<wmma::accumulator, 16, 16, 16, float> acc[8];
#pragma unroll
        for (int j = 0; j < 8; j++) wmma::fill_fragment(acc[j], 0.0f);
#pragma unroll
        for (int j = 0; j < 8; j++) {
            // B col-major: element B[c][n] at base[n*LDQ + c] == key rows as loaded
            wmma::fragment<wmma::matrix_b, 16, 16, 16, __half, wmma::col_major> b_hi, b_lo;
            wmma::load_matrix_sync(b_hi, kh + (j * 16) * LDQ, LDQ);
            wmma::load_matrix_sync(b_lo, kl + (j * 16) * LDQ, LDQ);
            wmma::mma_sync(acc[j], a_hi, b_hi, acc[j]);
            wmma::mma_sync(acc[j], a_hi, b_lo, acc[j]);
            wmma::mma_sync(acc[j], a_lo, b_hi, acc[j]);
        }

        // two half-tiles of 64 cols through the C buffer
#pragma unroll
        for (int hv = 0; hv < 2; ++hv) {
#pragma unroll
            for (int jj = 0; jj < 4; jj++)
                wmma::store_matrix_sync(C + (wid * 16) * LDC + jj * 16,
                                        acc[hv * 4 + jj], LDC, wmma::mem_row_major);
            __syncthreads();
            // epilogue: thread -> (row, cols c0..c0+31) of this 64-col half
            const float* Crow = C + row * LDC + c0;
            const float* ks   = ksq + hv * 64 + c0;
            __half hb[32];
#pragma unroll
            for (int i = 0; i < 32; i += 4) {
                float4 dv = *(const float4*)(Crow + i);
                float d0 = fmaxf(fmaf(-2.f, dv.x, qs + ks[i + 0]), 0.f);
                float d1 = fmaxf(fmaf(-2.f, dv.y, qs + ks[i + 1]), 0.f);
                float d2 = fmaxf(fmaf(-2.f, dv.z, qs + ks[i + 2]), 0.f);
                float d3 = fmaxf(fmaf(-2.f, dv.w, qs + ks[i + 3]), 0.f);
                float p0 = fast_exp_neg(-g * d0);
                float p1 = fast_exp_neg(-g * d1);
                float p2 = fast_exp_neg(-g * d2);
                float p3 = fast_exp_neg(-g * d3);
                rs += (p0 + p1) + (p2 + p3);
                *(__half2*)&hb[i]     = __floats2half2_rn(p0, p1);
                *(__half2*)&hb[i + 2] = __floats2half2_rn(p2, p3);
            }
            __half* Pp = P + ((size_t)bh * S_ + q0 + row) * S_ + k0 + hv * 64 + c0;
#pragma unroll
            for (int i = 0; i < 4; i++) ((uint4*)Pp)[i] = ((uint4*)hb)[i];
            __syncthreads();
        }
    }
    // combine the two col-half partners (adjacent lanes) and write rowsum
    rs += __shfl_xor_sync(0xffffffffu, rs, 1);
    if ((tid & 1) == 0) rowl[bh * S_ + q0 + row] = rs;
}

// ---------------- pipelined fp16 GEMM: C = epi(A[M,K] @ B[K,N] + bias) ----------------
template<int BM, int BN, int EPI>
__global__ void __launch_bounds__(128, 2) gemm_h(
    const __half* __restrict__ A, const __half* __restrict__ Bw,
    const float* __restrict__ bias, const float* __restrict__ Rres,
    void* __restrict__ Cout, int Mdim, int Ndim, int Kdim)
{
    constexpr int BK = 32;
    constexpr int STAGES = 3;
    constexpr int LDA = BK + 8;
    constexpr int LDB = BN + 8;
    constexpr int LDC = BN + 4;
    constexpr int WTM = BM / 2;
    constexpr int WTN = BN / 2;
    constexpr int FM  = WTM / 16;
    constexpr int FN  = WTN / 16;
    constexpr int A_STG = BM * LDA;
    constexpr int B_STG = BK * LDB;
    constexpr int CHB = BN / 8;

    extern __shared__ __align__(16) char smraw[];
    __half* As = (__half*)smraw;
    __half* Bs = As + STAGES * A_STG;

    const int tid = threadIdx.x;
    const int wid = tid >> 5;
    const int wm = wid >> 1, wn = wid & 1;
    const int bm0 = blockIdx.y * BM, bn0 = blockIdx.x * BN;

    wmma::fragment<wmma::accumulator, 16, 16, 16, float> acc[FM][FN];
#pragma unroll
    for (int i = 0; i < FM; i++)
#pragma unroll
        for (int j = 0; j < FN; j++) wmma::fill_fragment(acc[i][j], 0.0f);

    auto load_tile = [&](int stage, int k0) {
        __half* Ad = As + stage * A_STG;
        __half* Bd = Bs + stage * B_STG;
#pragma unroll
        for (int i = tid; i < BM * 4; i += 128) {
            int r = i >> 2, c = (i & 3) * 8;
            cp_async16(Ad + r * LDA + c, A + (size_t)(bm0 + r) * Kdim + k0 + c);
        }
#pragma unroll
        for (int i = tid; i < BK * CHB; i += 128) {
            int r = i / CHB, c = (i % CHB) * 8;
            cp_async16(Bd + r * LDB + c, Bw + (size_t)(k0 + r) * Ndim + bn0 + c);
        }
    };

    const int KT = Kdim / BK;
#pragma unroll
    for (int s = 0; s < STAGES - 1; ++s) {
        if (s < KT) load_tile(s, s * BK);
        cp_commit();
    }

    int read = 0, write = STAGES - 1;
    for (int it = 0; it < KT; ++it) {
        asm volatile("cp.async.wait_group %0;\n" :: "n"(STAGES - 2));
        __syncthreads();
        int knext = (it + STAGES - 1) * BK;
        if (knext < Kdim) load_tile(write, knext);
        cp_commit();

        const __half* Asr = As + read * A_STG;
        const __half* Bsr = Bs + read * B_STG;
#pragma unroll
        for (int kk = 0; kk < BK; kk += 16) {
            wmma::fragment<wmma::matrix_a, 16, 16, 16, __half, wmma::row_major> af[FM];
            wmma::fragment<wmma::matrix_b, 16, 16, 16, __half, wmma::row_major> bf[FN];
#pragma unroll
            for (int i = 0; i < FM; i++)
                wmma::load_matrix_sync(af[i], Asr + (wm * WTM + i * 16) * LDA + kk, LDA);
#pragma unroll
            for (int j = 0; j < FN; j++)
                wmma::load_matrix_sync(bf[j], Bsr + kk * LDB + wn * WTN + j * 16, LDB);
#pragma unroll
            for (int i = 0; i < FM; i++)
#pragma unroll
                for (int j = 0; j < FN; j++)
                    wmma::mma_sync(acc[i][j], af[i], bf[j], acc[i][j]);
        }
        read = (read + 1) % STAGES;
        write = (write + 1) % STAGES;
    }

    asm volatile("cp.async.wait_group 0;\n" ::);
    __syncthreads();

    float* Cs = (float*)smraw;
#pragma unroll
    for (int i = 0; i < FM; i++)
#pragma unroll
        for (int j = 0; j < FN; j++)
            wmma::store_matrix_sync(Cs + (wm * WTM + i * 16) * LDC + wn * WTN + j * 16,
                                    acc[i][j], LDC, wmma::mem_row_major);
    __syncthreads();

#pragma unroll 4
    for (int i = tid; i < BM * (BN / 4); i += 128) {
        int r = i / (BN / 4), c = (i % (BN / 4)) * 4;
        float4 v = *(float4*)&Cs[r * LDC + c];
        float4 bb = *(const float4*)(bias + bn0 + c);
        v.x += bb.x; v.y += bb.y; v.z += bb.z; v.w += bb.w;
        size_t off = (size_t)(bm0 + r) * Ndim + bn0 + c;
        if (EPI == EPI_BIAS_F32) {
            *(float4*)((float*)Cout + off) = v;
        } else if (EPI == EPI_RES_F32) {
            float4 rr = *(const float4*)(Rres + off);
            v.x += rr.x; v.y += rr.y; v.z += rr.z; v.w += rr.w;
            *(float4*)((float*)Cout + off) = v;
        } else if (EPI == EPI_GELU_H) {
            v.x = 0.5f * v.x * (1.0f + erff(v.x * 0.70710678118654752f));
            v.y = 0.5f * v.y * (1.0f + erff(v.y * 0.70710678118654752f));
            v.z = 0.5f * v.z * (1.0f + erff(v.z * 0.70710678118654752f));
            v.w = 0.5f * v.w * (1.0f + erff(v.w * 0.70710678118654752f));
            __half2* yp = (__half2*)((__half*)Cout + off);
            yp[0] = __floats2half2_rn(v.x, v.y);
            yp[1] = __floats2half2_rn(v.z, v.w);
        } else {
            __half2* yp = (__half2*)((__half*)Cout + off);
            yp[0] = __floats2half2_rn(v.x, v.y);
            yp[1] = __floats2half2_rn(v.z, v.w);
        }
    }
}

// ---------------- PV: attn = fp16((P @ V) / rowl), fp16 HMMA pipelined GEMM ----
__global__ void __launch_bounds__(256, 2) pv_pipe(
    const __half* __restrict__ P, const float* __restrict__ rowl,
    const __half* __restrict__ V, __half* __restrict__ O)
{
    constexpr int BM = 128, BN = 64, BK = 32, STAGES = 3;
    constexpr int LDA = BK + 8;
    constexpr int LDB = BN + 8;
    constexpr int LDC = BN + 4;
    constexpr int A_STG = BM * LDA;
    constexpr int B_STG = BK * LDB;

    extern __shared__ __align__(16) char smraw[];
    __half* As = (__half*)smraw;
    __half* Bs = As + STAGES * A_STG;
    float* linv = (float*)(smraw + STAGES * (A_STG + B_STG) * 2);

    const int tid = threadIdx.x;
    const int wid = tid >> 5;
    const int bh = blockIdx.y;
    const int b = bh >> 4, h = bh & 15;
    const int q0 = blockIdx.x * BM;

    const __half* Ab = P + (size_t)bh * S_ * S_;
    const __half* Bb = V + (size_t)b * S_ * D_ + h * DH_;

    if (tid < BM) linv[tid] = 1.0f / rowl[bh * S_ + q0 + tid];

    wmma::fragment<wmma::accumulator, 16, 16, 16, float> acc[4];
#pragma unroll
    for (int j = 0; j < 4; j++) wmma::fill_fragment(acc[j], 0.0f);

    auto load_tile = [&](int stage, int k0) {
        __half* Ad = As + stage * A_STG;
        __half* Bd = Bs + stage * B_STG;
#pragma unroll
        for (int i = tid; i < BM * 4; i += 256) {
            int r = i >> 2, c = (i & 3) * 8;
            cp_async16(Ad + r * LDA + c, Ab + (size_t)(q0 + r) * S_ + k0 + c);
        }
#pragma unroll
        for (int i = tid; i < BK * 8; i += 256) {
            int r = i >> 3, c = (i & 7) * 8;
            cp_async16(Bd + r * LDB + c, Bb + (size_t)(k0 + r) * D_ + c);
        }
    };

    constexpr int KT = S_ / BK;
#pragma unroll
    for (int s = 0; s < STAGES - 1; ++s) {
        load_tile(s, s * BK);
        cp_commit();
    }

    int read = 0, write = STAGES - 1;
    for (int it = 0; it < KT; ++it) {
        asm volatile("cp.async.wait_group %0;\n" :: "n"(STAGES - 2));
        __syncthreads();
        int knext = (it + STAGES - 1) * BK;
        if (knext < S_) load_tile(write, knext);
        cp_commit();

        const __half* Asr = As + read * A_STG;
        const __half* Bsr = Bs + read * B_STG;
#pragma unroll
        for (int kk = 0; kk < BK; kk += 16) {
            wmma::fragment<wmma::matrix_a, 16, 16, 16, __half, wmma::row_major> af;
            wmma::load_matrix_sync(af, Asr + (wid * 16) * LDA + kk, LDA);
#pragma unroll
            for (int j = 0; j < 4; j++) {
                wmma::fragment<wmma::matrix_b, 16, 16, 16, __half, wmma::row_major> bf;
                wmma::load_matrix_sync(bf, Bsr + kk * LDB + j * 16, LDB);
                wmma::mma_sync(acc[j], af, bf, acc[j]);
            }
        }
        read = (read + 1) % STAGES;
        write = (write + 1) % STAGES;
    }

    asm volatile("cp.async.wait_group 0;\n" ::);
    __syncthreads();

    float* Cs = (float*)smraw;
#pragma unroll
    for (int j = 0; j < 4; j++)
        wmma::store_matrix_sync(Cs + (wid * 16) * LDC + j * 16, acc[j], LDC, wmma::mem_row_major);
    __syncthreads();

#pragma unroll 4
    for (int i = tid; i < BM * 16; i += 256) {
        int r = i >> 4, c = (i & 15) * 4;
        float4 v = *(float4*)&Cs[r * LDC + c];
        float li = linv[r];
        v.x *= li; v.y *= li; v.z *= li; v.w *= li;
        __half2* yp = (__half2*)(O + ((size_t)(b * S_ + q0 + r)) * D_ + h * DH_ + c);
        yp[0] = __floats2half2_rn(v.x, v.y);
        yp[1] = __floats2half2_rn(v.z, v.w);
    }
}

// ---------------- LayerNorm D=1024, vectorized (fp32 or fp16 output) -----------
template<bool HOUT>
__global__ void ln1024(const float* __restrict__ x, const float* __restrict__ gm,
                       const float* __restrict__ bt, void* __restrict__ y)
{
    const int row = blockIdx.x;
    const int tid = threadIdx.x;
    float4 v = ((const float4*)x)[(size_t)row * 256 + tid];
    float s  = (v.x + v.y) + (v.z + v.w);
    float s2 = fmaf(v.x, v.x, fmaf(v.y, v.y, fmaf(v.z, v.z, v.w * v.w)));
    __shared__ float red[2][8];
    const int lane = tid & 31, wid = tid >> 5;
#pragma unroll
    for (int off = 16; off; off >>= 1) {
        s  += __shfl_xor_sync(0xffffffffu, s, off);
        s2 += __shfl_xor_sync(0xffffffffu, s2, off);
    }
    if (lane == 0) { red[0][wid] = s; red[1][wid] = s2; }
    __syncthreads();
    if (wid == 0) {
        s  = (lane < 8) ? red[0][lane] : 0.f;
        s2 = (lane < 8) ? red[1][lane] : 0.f;
#pragma unroll
        for (int off = 4; off; off >>= 1) {
            s  += __shfl_xor_sync(0xffffffffu, s, off);
            s2 += __shfl_xor_sync(0xffffffffu, s2, off);
        }
        if (lane == 0) { red[0][0] = s; red[1][0] = s2; }
    }
    __syncthreads();
    s = red[0][0]; s2 = red[1][0];
    const float mean = s * (1.0f / 1024.0f);
    const float var  = s2 * (1.0f / 1024.0f) - mean * mean;
    const float inv  = rsqrtf(var + 1e-5f);
    float4 g4 = ((const float4*)gm)[tid];
    float4 b4 = ((const float4*)bt)[tid];
    float4 o;
    o.x = (v.x - mean) * inv * g4.x + b4.x;
    o.y = (v.y - mean) * inv * g4.y + b4.y;
    o.z = (v.z - mean) * inv * g4.z + b4.z;
    o.w = (v.w - mean) * inv * g4.w + b4.w;
    if (HOUT) {
        __half2* yp = (__half2*)((__half*)y + (size_t)row * 1024 + tid * 4);
        yp[0] = __floats2half2_rn(o.x, o.y);
        yp[1] = __floats2half2_rn(o.z, o.w);
    } else {
        ((float4*)y)[(size_t)row * 256 + tid] = o;
    }
}

// ---------------- generic LayerNorm (small Dd) ----------------
__global__ void ln_small(const float* __restrict__ x, const float* __restrict__ gm,
                         const float* __restrict__ bt, float* __restrict__ y, int Dd)
{
    const int row = blockIdx.x;
    const float* xr = x + (size_t)row * Dd;
    float s = 0.f, s2 = 0.f;
    for (int i = threadIdx.x; i < Dd; i += blockDim.x) {
        float v = xr[i]; s += v; s2 = fmaf(v, v, s2);
    }
#pragma unroll
    for (int off = 16; off; off >>= 1) {
        s  += __shfl_xor_sync(0xffffffffu, s, off);
        s2 += __shfl_xor_sync(0xffffffffu, s2, off);
    }
    s  = __shfl_sync(0xffffffffu, s, 0);
    s2 = __shfl_sync(0xffffffffu, s2, 0);
    const float mean = s / Dd;
    const float var  = s2 / Dd - mean * mean;
    const float inv  = rsqrtf(var + 1e-5f);
    float* yr = y + (size_t)row * Dd;
    for (int i = threadIdx.x; i < Dd; i += blockDim.x)
        yr[i] = (xr[i] - mean) * inv * gm[i] + bt[i];
}

// ---------------- launch ----------------
extern "C" void kernel_launch(void* const* d_in, const int* in_sizes, int n_in,
                              void* d_out, int out_size)
{
    const float* h    = (const float*)d_in[0];
    const float* z    = (const float*)d_in[1];
    const float* wv   = (const float*)d_in[2];
    const float* bv   = (const float*)d_in[3];
    const float* wca  = (const float*)d_in[4];
    const float* bca  = (const float*)d_in[5];
    const float* wcn  = (const float*)d_in[6];
    const float* bcn  = (const float*)d_in[7];
    const float* wo   = (const float*)d_in[8];
    const float* bo   = (const float*)d_in[9];
    const float* gamma= (const float*)d_in[10];
    const float* w1   = (const float*)d_in[11];
    const float* b1   = (const float*)d_in[12];
    const float* w2   = (const float*)d_in[13];
    const float* b2   = (const float*)d_in[14];
    const float* ln1g = (const float*)d_in[15];
    const float* ln1b = (const float*)d_in[16];
    const float* ln2g = (const float*)d_in[17];
    const float* ln2b = (const float*)d_in[18];
    const float* lncg = (const float*)d_in[19];
    const float* lncb = (const float*)d_in[20];

    float* out_h = (float*)d_out;
    float* out_z = out_h + (size_t)BS_ * D_;

    float  *p_zh, *p_rl, *p_h1, *p_ztmp, *p_zsq;
    __half *p_hn, *p_val, *p_attn, *p_hn2, *p_mid, *p_P, *p_zhi, *p_zlo;
    __half *p_wv, *p_wca, *p_wcn, *p_wo, *p_w1, *p_w2, *p_z;
    cudaGetSymbolAddress((void**)&p_zh,  g_zh);
    cudaGetSymbolAddress((void**)&p_rl,  g_rowl);
    cudaGetSymbolAddress((void**)&p_h1,  g_h1);
    cudaGetSymbolAddress((void**)&p_ztmp,g_ztmp);
    cudaGetSymbolAddress((void**)&p_zsq, g_zsq);
    cudaGetSymbolAddress((void**)&p_hn,  g_hn_h);
    cudaGetSymbolAddress((void**)&p_val, g_val_h);
    cudaGetSymbolAddress((void**)&p_attn,g_attn_h);
    cudaGetSymbolAddress((void**)&p_hn2, g_hn2_h);
    cudaGetSymbolAddress((void**)&p_mid, g_mid_h);
    cudaGetSymbolAddress((void**)&p_P,   g_P_h);
    cudaGetSymbolAddress((void**)&p_zhi, g_zhi);
    cudaGetSymbolAddress((void**)&p_zlo, g_zlo);
    cudaGetSymbolAddress((void**)&p_wv,  g_wv_h);
    cudaGetSymbolAddress((void**)&p_wca, g_wca_h);
    cudaGetSymbolAddress((void**)&p_wcn, g_wcn_h);
    cudaGetSymbolAddress((void**)&p_wo,  g_wo_h);
    cudaGetSymbolAddress((void**)&p_w1,  g_w1_h);
    cudaGetSymbolAddress((void**)&p_w2,  g_w2_h);
    cudaGetSymbolAddress((void**)&p_z,   g_z_h);

    constexpr int SM128 = ((3 * (128*40 + 32*136) * 2) > (128*132*4)) ? (3 * (128*40 + 32*136) * 2) : (128*132*4);
    constexpr int SM64  = ((3 * (64*40 + 32*72) * 2) > (64*68*4)) ? (3 * (64*40 + 32*72) * 2) : (64*68*4);
    constexpr int SMPV  = 3 * (128*40 + 32*72) * 2 + 512;
    cudaFuncSetAttribute(gemm_h<128,128,EPI_BIAS_F32>, cudaFuncAttributeMaxDynamicSharedMemorySize, SM128);
    cudaFuncSetAttribute(gemm_h<128,128,EPI_RES_F32 >, cudaFuncAttributeMaxDynamicSharedMemorySize, SM128);
    cudaFuncSetAttribute(gemm_h<128,128,EPI_GELU_H  >, cudaFuncAttributeMaxDynamicSharedMemorySize, SM128);
    cudaFuncSetAttribute(gemm_h<128,128,EPI_BIAS_H  >, cudaFuncAttributeMaxDynamicSharedMemorySize, SM128);
    cudaFuncSetAttribute(gemm_h< 64, 64,EPI_RES_F32 >, cudaFuncAttributeMaxDynamicSharedMemorySize, SM64);
    cudaFuncSetAttribute(pv_pipe,                      cudaFuncAttributeMaxDynamicSharedMemorySize, SMPV);
    cudaFuncSetAttribute(score_mma,                    cudaFuncAttributeMaxDynamicSharedMemorySize, SC_SMEM);

    auto cvt = [&](const float* src, __half* dst, int n) {
        int n4 = n / 4;
        f2h_kernel<<<(n4 + 255) / 256, 256>>>(src, dst, n4);
    };

    cvt(wv,  p_wv,  D_*D_);
    cvt(z,   p_z,   BS_*DC_);
    cvt(wca, p_wca, DC_*H_*HC_);
    ln1024<true><<<BS_, 256>>>(h, ln1g, ln1b, p_hn);
    // zh = z @ wca + bca  (fp32, for the Dekker split)
    gemm_h<128,128,EPI_BIAS_F32><<<dim3(2, BS_/128), 128, SM128>>>(p_z, p_wca, bca, nullptr, p_zh, BS_, 256, DC_);
    // value = fp16(hn @ wv + bv)
    gemm_h<128,128,EPI_BIAS_H><<<dim3(D_/128, BS_/128), 128, SM128>>>(p_hn, p_wv, bv, nullptr, p_val, BS_, D_, D_);
    cvt(wcn, p_wcn, D_*DC_);
    cvt(wo,  p_wo,  D_*D_);
    cvt(w1,  p_w1,  D_*MFF_);
    cvt(w2,  p_w2,  MFF_*D_);
    // Dekker split + norms
    score_prep<<<(BS_*H_ + 255) / 256, 256>>>(p_zh, p_zhi, p_zlo, p_zsq);
    // z_tmp = z + (hn @ wcn + bcn)
    gemm_h<64,64,EPI_RES_F32><<<dim3(1, BS_/64), 128, SM64>>>(p_hn, p_wcn, bcn, z, p_ztmp, BS_, DC_, D_);
    // P = fp16(exp(-g*dist)), rowl via tensor-core distance
    score_mma<<<dim3(S_/128, BH_), 256, SC_SMEM>>>(p_zhi, p_zlo, p_zsq, gamma, p_P, p_rl);
    // attn = fp16((P @ V) / rowl)
    pv_pipe<<<dim3(S_/128, BH_), 256, SMPV>>>(p_P, p_rl, p_val, p_attn);
    // h1 = h + (attn @ wo + bo)
    gemm_h<128,128,EPI_RES_F32><<<dim3(D_/128, BS_/128), 128, SM128>>>(p_attn, p_wo, bo, h, p_h1, BS_, D_, D_);
    // hn2 = fp16(LN2(h1))
    ln1024<true><<<BS_, 256>>>(p_h1, ln2g, ln2b, p_hn2);
    // mid = fp16(gelu(hn2 @ w1 + b1))
    gemm_h<128,128,EPI_GELU_H><<<dim3(MFF_/128, BS_/128), 128, SM128>>>(p_hn2, p_w1, b1, nullptr, p_mid, BS_, MFF_, D_);
    // out_h = h1 + (mid @ w2 + b2)
    gemm_h<128,128,EPI_RES_F32><<<dim3(D_/128, BS_/128), 128, SM128>>>(p_mid, p_w2, b2, p_h1, out_h, BS_, D_, MFF_);
    // out_z = LN_c(z_tmp)
    ln_small<<<BS_, 32>>>(p_ztmp, lncg, lncb, out_z, DC_);
}

// round 14
// speedup vs baseline: 5.6327x; 1.0932x over previous
#include <cuda_runtime.h>
#include <cuda_fp16.h>
#include <mma.h>
#include <math.h>

using namespace nvcuda;

#define B_   2
#define S_   2048
#define D_   1024
#define H_   16
#define DC_  64
#define HC_  16
#define MFF_ 4096
#define DH_  64
#define BS_  (B_*S_)      // 4096
#define BH_  (B_*H_)      // 32

// ---------------- scratch (static device globals; no allocation) ----------------
__device__ float  g_zh  [BS_*H_*HC_];
__device__ float  g_h1  [BS_*D_];
__device__ float  g_ztmp[BS_*DC_];
__device__ float  g_zsq [BS_*H_];
// half activations / operands
__device__ __half g_hn_h  [BS_*D_];
__device__ __half g_val_h [BS_*D_];
__device__ __half g_attn_h[BS_*D_];
__device__ __half g_hn2_h [BS_*D_];
__device__ __half g_mid_h [BS_*MFF_];
__device__ __half g_zhi   [BS_*H_*HC_];  // hi part of zh (Dekker split)
__device__ __half g_zlo   [BS_*H_*HC_];  // lo part
// half weight copies
__device__ __half g_wv_h [D_*D_];
__device__ __half g_wca_h[DC_*H_*HC_];
__device__ __half g_wcn_h[D_*DC_];
__device__ __half g_wo_h [D_*D_];
__device__ __half g_w1_h [D_*MFF_];
__device__ __half g_w2_h [MFF_*D_];
__device__ __half g_z_h  [BS_*DC_];

// exp(s) for s <= 0, FMA-pipe only (no MUFU). ~2.4e-6 max rel err.
__device__ __forceinline__ float fast_exp_neg(float s) {
    float y = fmaxf(s * 1.4426950408889634f, -126.0f);
    float z = y + 12582912.0f;
    float r = z - 12582912.0f;
    float f = y - r;
    int   iz = __float_as_int(z);
    float sc = __int_as_float((iz + (127 - 0x400000)) << 23);
    float p = 0.0013333558f;
    p = fmaf(p, f, 0.0096181291f);
    p = fmaf(p, f, 0.0555041087f);
    p = fmaf(p, f, 0.2402265070f);
    p = fmaf(p, f, 0.6931471806f);
    p = fmaf(p, f, 1.0f);
    return sc * p;
}

enum { EPI_BIAS_F32 = 0, EPI_RES_F32 = 1, EPI_GELU_H = 2, EPI_BIAS_H = 3 };

__device__ __forceinline__ void cp_async16(void* smem_dst, const void* gmem_src) {
    unsigned sa = (unsigned)__cvta_generic_to_shared(smem_dst);
    asm volatile("cp.async.cg.shared.global [%0], [%1], 16;\n" :: "r"(sa), "l"(gmem_src));
}
__device__ __forceinline__ void cp_commit() {
    asm volatile("cp.async.commit_group;\n" ::);
}

// ---------------- fp32 -> fp16 conversion (float4 -> 4 halves) ----------------
__global__ void f2h_kernel(const float* __restrict__ x, __half* __restrict__ y, int n4) {
    int i = blockIdx.x * blockDim.x + threadIdx.x;
    if (i < n4) {
        float4 v = ((const float4*)x)[i];
        __half2* yp = (__half2*)y;
        yp[2*i]   = __floats2half2_rn(v.x, v.y);
        yp[2*i+1] = __floats2half2_rn(v.z, v.w);
    }
}

// ---------------- score prep: Dekker split zh -> (hi, lo) fp16 + per-head norms --
__global__ void score_prep(const float* __restrict__ zh, __half* __restrict__ hi,
                           __half* __restrict__ lo, float* __restrict__ zsq)
{
    int t = blockIdx.x * blockDim.x + threadIdx.x;
    if (t >= BS_ * H_) return;
    const float4* src = (const float4*)(zh + (size_t)t * 16);
    __half hb[16], lb[16];
    float s = 0.f;
#pragma unroll
    for (int q = 0; q < 4; q++) {
        float4 v = src[q];
        float vv[4] = {v.x, v.y, v.z, v.w};
#pragma unroll
        for (int j = 0; j < 4; j++) {
            float x = vv[j];
            __half hx = __float2half_rn(x);
            float  rx = x - __half2float(hx);
            hb[q*4+j] = hx;
            lb[q*4+j] = __float2half_rn(rx);
            s = fmaf(x, x, s);
        }
    }
    ((uint4*)(hi + (size_t)t * 16))[0] = ((uint4*)hb)[0];
    ((uint4*)(hi + (size_t)t * 16))[1] = ((uint4*)hb)[1];
    ((uint4*)(lo + (size_t)t * 16))[0] = ((uint4*)lb)[0];
    ((uint4*)(lo + (size_t)t * 16))[1] = ((uint4*)lb)[1];
    zsq[t] = s;
}

// ---------------- fused flash attention (all tensor-core) ----------------------
// Per CTA: 128 q-rows of one (b,h). 16 k-tiles of 128:
//   score (3-HMMA Dekker dot) -> exp epilogue -> P tile in SMEM (fp16)
//   -> PV HMMAs against cp.async-prefetched V tile -> persistent O accumulators.
// Row max is exactly 0 => p=exp(s), divide by rowsum at the very end.
// smem (bytes): qh 0, ql 6144, kh 12288, kl 18432, qsq 24576, ksq 25088,
//               C 25600 (128x68 f32), Ph 60416 (128x136 f16), Vs 95232 (128x72 f16)
#define AT_QH   0
#define AT_QL   6144
#define AT_KH   12288
#define AT_KL   18432
#define AT_QSQ  24576
#define AT_KSQ  25088
#define AT_C    25600
#define AT_PH   60416
#define AT_VS   95232
#define AT_SMEM 113664

__global__ void __launch_bounds__(256, 1) attn_mma(
    const __half* __restrict__ zhi, const __half* __restrict__ zlo,
    const float* __restrict__ zsq, const float* __restrict__ gamma,
    const __half* __restrict__ V, __half* __restrict__ O)
{
    constexpr int LDQ = 24;   // halves
    constexpr int LDC = 68;   // floats
    constexpr int LDP = 136;  // halves
    constexpr int LDV = 72;   // halves
    extern __shared__ __align__(16) char smraw[];
    __half* qh  = (__half*)(smraw + AT_QH);
    __half* ql  = (__half*)(smraw + AT_QL);
    __half* kh  = (__half*)(smraw + AT_KH);
    __half* kl  = (__half*)(smraw + AT_KL);
    float*  qsq = (float*)(smraw + AT_QSQ);
    float*  ksq = (float*)(smraw + AT_KSQ);
    float*  C   = (float*)(smraw + AT_C);
    __half* Ph  = (__half*)(smraw + AT_PH);
    __half* Vs  = (__half*)(smraw + AT_VS);

    const int tid = threadIdx.x;
    const int wid = tid >> 5;
    const int bh = blockIdx.y;
    const int b = bh >> 4, h = bh & 15;
    const int q0 = blockIdx.x * 128;

    const float gx = gamma[h];
    const float g = (gx > 20.f) ? gx : log1pf(__expf(gx));
    const __half* Vb = V + (size_t)b * S_ * D_ + h * DH_;

    // load q tiles (hi/lo) + norms
    {
        int r = tid >> 1, part = tid & 1;
        size_t go = ((size_t)(b * S_ + q0 + r)) * (H_ * HC_) + h * 16 + part * 8;
        *(uint4*)(qh + r * LDQ + part * 8) = *(const uint4*)(zhi + go);
        *(uint4*)(ql + r * LDQ + part * 8) = *(const uint4*)(zlo + go);
        if (part == 0) qsq[r] = zsq[(size_t)(b * S_ + q0 + r) * H_ + h];
    }
    __syncthreads();

    wmma::fragment<wmma::matrix_a, 16, 16, 16, __half, wmma::row_major> a_hi, a_lo;
    wmma::load_matrix_sync(a_hi, qh + (wid * 16) * LDQ, LDQ);
    wmma::load_matrix_sync(a_lo, ql + (wid * 16) * LDQ, LDQ);

    const int row = tid >> 1;
    const int c0  = (tid & 1) * 32;
    const float qs = qsq[row];
    float rs = 0.f;

    wmma::fragment<wmma::accumulator, 16, 16, 16, float> acc_o[4];
#pragma unroll
    for (int j = 0; j < 4; j++) wmma::fill_fragment(acc_o[j], 0.0f);

    for (int kt = 0; kt < 16; ++kt) {
        const int k0 = kt * 128;
        __syncthreads();   // prev PV done with Ph/Vs; prev epilogue done with kh/ksq/C
        {
            int r = tid >> 1, part = tid & 1;
            size_t go = ((size_t)(b * S_ + k0 + r)) * (H_ * HC_) + h * 16 + part * 8;
            *(uint4*)(kh + r * LDQ + part * 8) = *(const uint4*)(zhi + go);
            *(uint4*)(kl + r * LDQ + part * 8) = *(const uint4*)(zlo + go);
            if (part == 0) ksq[r] = zsq[(size_t)(b * S_ + k0 + r) * H_ + h];
        }
        // prefetch V tile [128 x 64] halves
#pragma unroll
        for (int i = tid; i < 128 * 8; i += 256) {
            int r = i >> 3, c = (i & 7) * 8;
            cp_async16(Vs + r * LDV + c, Vb + (size_t)(k0 + r) * D_ + c);
        }
        cp_commit();
        __syncthreads();

        // ---- score MMAs: warp wid -> q rows wid*16..+15 x all 128 k cols
        wmma::fragment<wmma::accumulator, 16, 16, 16, float> acc[8];
#pragma unroll
        for (int j = 0; j < 8; j++) wmma::fill_fragment(acc[j], 0.0f);
#pragma unroll
        for (int j = 0; j < 8; j++) {
            wmma::fragment<wmma::matrix_b, 16, 16, 16, __half, wmma::col_major> b_hi, b_lo;
            wmma::load_matrix_sync(b_hi, kh + (j * 16) * LDQ, LDQ);
            wmma::load_matrix_sync(b_lo, kl + (j * 16) * LDQ, LDQ);
            wmma::mma_sync(acc[j], a_hi, b_hi, acc[j]);
            wmma::mma_sync(acc[j], a_hi, b_lo, acc[j]);
            wmma::mma_sync(acc[j], a_lo, b_hi, acc[j]);
        }

        // ---- exp epilogue into SMEM Ph, two 64-col halves via C buffer
#pragma unroll
        for (int hv = 0; hv < 2; ++hv) {
#pragma unroll
            for (int jj = 0; jj < 4; jj++)
                wmma::store_matrix_sync(C + (wid * 16) * LDC + jj * 16,
                                        acc[hv * 4 + jj], LDC, wmma::mem_row_major);
            __syncthreads();
            const float* Crow = C + row * LDC + c0;
            const float* ks   = ksq + hv * 64 + c0;
            __half hb[32];
#pragma unroll
            for (int i = 0; i < 32; i += 4) {
                float4 dv = *(const float4*)(Crow + i);
                float d0 = fmaxf(fmaf(-2.f, dv.x, qs + ks[i + 0]), 0.f);
                float d1 = fmaxf(fmaf(-2.f, dv.y, qs + ks[i + 1]), 0.f);
                float d2 = fmaxf(fmaf(-2.f, dv.z, qs + ks[i + 2]), 0.f);
                float d3 = fmaxf(fmaf(-2.f, dv.w, qs + ks[i + 3]), 0.f);
                float p0 = fast_exp_neg(-g * d0);
                float p1 = fast_exp_neg(-g * d1);
                float p2 = fast_exp_neg(-g * d2);
                float p3 = fast_exp_neg(-g * d3);
                rs += (p0 + p1) + (p2 + p3);
                *(__half2*)&hb[i]     = __floats2half2_rn(p0, p1);
                *(__half2*)&hb[i + 2] = __floats2half2_rn(p2, p3);
            }
            __half* Pp = Ph + (size_t)row * LDP + hv * 64 + c0;
#pragma unroll
            for (int i = 0; i < 4; i++) ((uint4*)Pp)[i] = ((uint4*)hb)[i];
            __syncthreads();
        }

        // ---- PV: O += P(128x128) @ V(128x64); warp's A rows are its own Ph band
        asm volatile("cp.async.wait_group 0;\n" ::);
        __syncthreads();
#pragma unroll
        for (int kk = 0; kk < 128; kk += 16) {
            wmma::fragment<wmma::matrix_a, 16, 16, 16, __half, wmma::row_major> af;
            wmma::load_matrix_sync(af, Ph + (wid * 16) * LDP + kk, LDP);
#pragma unroll
            for (int j = 0; j < 4; j++) {
                wmma::fragment<wmma::matrix_b, 16, 16, 16, __half, wmma::row_major> bf;
                wmma::load_matrix_sync(bf, Vs + kk * LDV + j * 16, LDV);
                wmma::mma_sync(acc_o[j], af, bf, acc_o[j]);
            }
        }
    }

    // rowsum combine (adjacent lanes are the two col-halves of a row)
    rs += __shfl_xor_sync(0xffffffffu, rs, 1);
    if ((tid & 1) == 0) qsq[row] = 1.0f / rs;   // qsq reused as linv
    // store O accumulators to C
#pragma unroll
    for (int j = 0; j < 4; j++)
        wmma::store_matrix_sync(C + (wid * 16) * LDC + j * 16, acc_o[j], LDC, wmma::mem_row_major);
    __syncthreads();

#pragma unroll 4
    for (int i = tid; i < 128 * 16; i += 256) {
        int r = i >> 4, c = (i & 15) * 4;
        float4 v = *(float4*)&C[r * LDC + c];
        float li = qsq[r];
        v.x *= li; v.y *= li; v.z *= li; v.w *= li;
        __half2* yp = (__half2*)(O + ((size_t)(b * S_ + q0 + r)) * D_ + h * DH_ + c);
        yp[0] = __floats2half2_rn(v.x, v.y);
        yp[1] = __floats2half2_rn(v.z, v.w);
    }
}

// ---------------- pipelined fp16 GEMM: C = epi(A[M,K] @ B[K,N] + bias) ----------------
template<int BM, int BN, int EPI>
__global__ void __launch_bounds__(128, 2) gemm_h(
    const __half* __restrict__ A, const __half* __restrict__ Bw,
    const float* __restrict__ bias, const float* __restrict__ Rres,
    void* __restrict__ Cout, int Mdim, int Ndim, int Kdim)
{
    constexpr int BK = 32;
    constexpr int STAGES = 3;
    constexpr int LDA = BK + 8;
    constexpr int LDB = BN + 8;
    constexpr int LDC = BN + 4;
    constexpr int WTM = BM / 2;
    constexpr int WTN = BN / 2;
    constexpr int FM  = WTM / 16;
    constexpr int FN  = WTN / 16;
    constexpr int A_STG = BM * LDA;
    constexpr int B_STG = BK * LDB;
    constexpr int CHB = BN / 8;

    extern __shared__ __align__(16) char smraw[];
    __half* As = (__half*)smraw;
    __half* Bs = As + STAGES * A_STG;

    const int tid = threadIdx.x;
    const int wid = tid >> 5;
    const int wm = wid >> 1, wn = wid & 1;
    const int bm0 = blockIdx.y * BM, bn0 = blockIdx.x * BN;

    wmma::fragment<wmma::accumulator, 16, 16, 16, float> acc[FM][FN];
#pragma unroll
    for (int i = 0; i < FM; i++)
#pragma unroll
        for (int j = 0; j < FN; j++) wmma::fill_fragment(acc[i][j], 0.0f);

    auto load_tile = [&](int stage, int k0) {
        __half* Ad = As + stage * A_STG;
        __half* Bd = Bs + stage * B_STG;
#pragma unroll
        for (int i = tid; i < BM * 4; i += 128) {
            int r = i >> 2, c = (i & 3) * 8;
            cp_async16(Ad + r * LDA + c, A + (size_t)(bm0 + r) * Kdim + k0 + c);
        }
#pragma unroll
        for (int i = tid; i < BK * CHB; i += 128) {
            int r = i / CHB, c = (i % CHB) * 8;
            cp_async16(Bd + r * LDB + c, Bw + (size_t)(k0 + r) * Ndim + bn0 + c);
        }
    };

    const int KT = Kdim / BK;
#pragma unroll
    for (int s = 0; s < STAGES - 1; ++s) {
        if (s < KT) load_tile(s, s * BK);
        cp_commit();
    }

    int read = 0, write = STAGES - 1;
    for (int it = 0; it < KT; ++it) {
        asm volatile("cp.async.wait_group %0;\n" :: "n"(STAGES - 2));
        __syncthreads();
        int knext = (it + STAGES - 1) * BK;
        if (knext < Kdim) load_tile(write, knext);
        cp_commit();

        const __half* Asr = As + read * A_STG;
        const __half* Bsr = Bs + read * B_STG;
#pragma unroll
        for (int kk = 0; kk < BK; kk += 16) {
            wmma::fragment<wmma::matrix_a, 16, 16, 16, __half, wmma::row_major> af[FM];
            wmma::fragment<wmma::matrix_b, 16, 16, 16, __half, wmma::row_major> bf[FN];
#pragma unroll
            for (int i = 0; i < FM; i++)
                wmma::load_matrix_sync(af[i], Asr + (wm * WTM + i * 16) * LDA + kk, LDA);
#pragma unroll
            for (int j = 0; j < FN; j++)
                wmma::load_matrix_sync(bf[j], Bsr + kk * LDB + wn * WTN + j * 16, LDB);
#pragma unroll
            for (int i = 0; i < FM; i++)
#pragma unroll
                for (int j = 0; j < FN; j++)
                    wmma::mma_sync(acc[i][j], af[i], bf[j], acc[i][j]);
        }
        read = (read + 1) % STAGES;
        write = (write + 1) % STAGES;
    }

    asm volatile("cp.async.wait_group 0;\n" ::);
    __syncthreads();

    float* Cs = (float*)smraw;
#pragma unroll
    for (int i = 0; i < FM; i++)
#pragma unroll
        for (int j = 0; j < FN; j++)
            wmma::store_matrix_sync(Cs + (wm * WTM + i * 16) * LDC + wn * WTN + j * 16,
                                    acc[i][j], LDC, wmma::mem_row_major);
    __syncthreads();

#pragma unroll 4
    for (int i = tid; i < BM * (BN / 4); i += 128) {
        int r = i / (BN / 4), c = (i % (BN / 4)) * 4;
        float4 v = *(float4*)&Cs[r * LDC + c];
        float4 bb = *(const float4*)(bias + bn0 + c);
        v.x += bb.x; v.y += bb.y; v.z += bb.z; v.w += bb.w;
        size_t off = (size_t)(bm0 + r) * Ndim + bn0 + c;
        if (EPI == EPI_BIAS_F32) {
            *(float4*)((float*)Cout + off) = v;
        } else if (EPI == EPI_RES_F32) {
            float4 rr = *(const float4*)(Rres + off);
            v.x += rr.x; v.y += rr.y; v.z += rr.z; v.w += rr.w;
            *(float4*)((float*)Cout + off) = v;
        } else if (EPI == EPI_GELU_H) {
            v.x = 0.5f * v.x * (1.0f + erff(v.x * 0.70710678118654752f));
            v.y = 0.5f * v.y * (1.0f + erff(v.y * 0.70710678118654752f));
            v.z = 0.5f * v.z * (1.0f + erff(v.z * 0.70710678118654752f));
            v.w = 0.5f * v.w * (1.0f + erff(v.w * 0.70710678118654752f));
            __half2* yp = (__half2*)((__half*)Cout + off);
            yp[0] = __floats2half2_rn(v.x, v.y);
            yp[1] = __floats2half2_rn(v.z, v.w);
        } else {
            __half2* yp = (__half2*)((__half*)Cout + off);
            yp[0] = __floats2half2_rn(v.x, v.y);
            yp[1] = __floats2half2_rn(v.z, v.w);
        }
    }
}

// ---------------- LayerNorm D=1024, vectorized (fp32 or fp16 output) -----------
template<bool HOUT>
__global__ void ln1024(const float* __restrict__ x, const float* __restrict__ gm,
                       const float* __restrict__ bt, void* __restrict__ y)
{
    const int row = blockIdx.x;
    const int tid = threadIdx.x;
    float4 v = ((const float4*)x)[(size_t)row * 256 + tid];
    float s  = (v.x + v.y) + (v.z + v.w);
    float s2 = fmaf(v.x, v.x, fmaf(v.y, v.y, fmaf(v.z, v.z, v.w * v.w)));
    __shared__ float red[2][8];
    const int lane = tid & 31, wid = tid >> 5;
#pragma unroll
    for (int off = 16; off; off >>= 1) {
        s  += __shfl_xor_sync(0xffffffffu, s, off);
        s2 += __shfl_xor_sync(0xffffffffu, s2, off);
    }
    if (lane == 0) { red[0][wid] = s; red[1][wid] = s2; }
    __syncthreads();
    if (wid == 0) {
        s  = (lane < 8) ? red[0][lane] : 0.f;
        s2 = (lane < 8) ? red[1][lane] : 0.f;
#pragma unroll
        for (int off = 4; off; off >>= 1) {
            s  += __shfl_xor_sync(0xffffffffu, s, off);
            s2 += __shfl_xor_sync(0xffffffffu, s2, off);
        }
        if (lane == 0) { red[0][0] = s; red[1][0] = s2; }
    }
    __syncthreads();
    s = red[0][0]; s2 = red[1][0];
    const float mean = s * (1.0f / 1024.0f);
    const float var  = s2 * (1.0f / 1024.0f) - mean * mean;
    const float inv  = rsqrtf(var + 1e-5f);
    float4 g4 = ((const float4*)gm)[tid];
    float4 b4 = ((const float4*)bt)[tid];
    float4 o;
    o.x = (v.x - mean) * inv * g4.x + b4.x;
    o.y = (v.y - mean) * inv * g4.y + b4.y;
    o.z = (v.z - mean) * inv * g4.z + b4.z;
    o.w = (v.w - mean) * inv * g4.w + b4.w;
    if (HOUT) {
        __half2* yp = (__half2*)((__half*)y + (size_t)row * 1024 + tid * 4);
        yp[0] = __floats2half2_rn(o.x, o.y);
        yp[1] = __floats2half2_rn(o.z, o.w);
    } else {
        ((float4*)y)[(size_t)row * 256 + tid] = o;
    }
}

// ---------------- generic LayerNorm (small Dd) ----------------
__global__ void ln_small(const float* __restrict__ x, const float* __restrict__ gm,
                         const float* __restrict__ bt, float* __restrict__ y, int Dd)
{
    const int row = blockIdx.x;
    const float* xr = x + (size_t)row * Dd;
    float s = 0.f, s2 = 0.f;
    for (int i = threadIdx.x; i < Dd; i += blockDim.x) {
        float v = xr[i]; s += v; s2 = fmaf(v, v, s2);
    }
#pragma unroll
    for (int off = 16; off; off >>= 1) {
        s  += __shfl_xor_sync(0xffffffffu, s, off);
        s2 += __shfl_xor_sync(0xffffffffu, s2, off);
    }
    s  = __shfl_sync(0xffffffffu, s, 0);
    s2 = __shfl_sync(0xffffffffu, s2, 0);
    const float mean = s / Dd;
    const float var  = s2 / Dd - mean * mean;
    const float inv  = rsqrtf(var + 1e-5f);
    float* yr = y + (size_t)row * Dd;
    for (int i = threadIdx.x; i < Dd; i += blockDim.x)
        yr[i] = (xr[i] - mean) * inv * gm[i] + bt[i];
}

// ---------------- launch ----------------
extern "C" void kernel_launch(void* const* d_in, const int* in_sizes, int n_in,
                              void* d_out, int out_size)
{
    const float* h    = (const float*)d_in[0];
    const float* z    = (const float*)d_in[1];
    const float* wv   = (const float*)d_in[2];
    const float* bv   = (const float*)d_in[3];
    const float* wca  = (const float*)d_in[4];
    const float* bca  = (const float*)d_in[5];
    const float* wcn  = (const float*)d_in[6];
    const float* bcn  = (const float*)d_in[7];
    const float* wo   = (const float*)d_in[8];
    const float* bo   = (const float*)d_in[9];
    const float* gamma= (const float*)d_in[10];
    const float* w1   = (const float*)d_in[11];
    const float* b1   = (const float*)d_in[12];
    const float* w2   = (const float*)d_in[13];
    const float* b2   = (const float*)d_in[14];
    const float* ln1g = (const float*)d_in[15];
    const float* ln1b = (const float*)d_in[16];
    const float* ln2g = (const float*)d_in[17];
    const float* ln2b = (const float*)d_in[18];
    const float* lncg = (const float*)d_in[19];
    const float* lncb = (const float*)d_in[20];

    float* out_h = (float*)d_out;
    float* out_z = out_h + (size_t)BS_ * D_;

    float  *p_zh, *p_h1, *p_ztmp, *p_zsq;
    __half *p_hn, *p_val, *p_attn, *p_hn2, *p_mid, *p_zhi, *p_zlo;
    __half *p_wv, *p_wca, *p_wcn, *p_wo, *p_w1, *p_w2, *p_z;
    cudaGetSymbolAddress((void**)&p_zh,  g_zh);
    cudaGetSymbolAddress((void**)&p_h1,  g_h1);
    cudaGetSymbolAddress((void**)&p_ztmp,g_ztmp);
    cudaGetSymbolAddress((void**)&p_zsq, g_zsq);
    cudaGetSymbolAddress((void**)&p_hn,  g_hn_h);
    cudaGetSymbolAddress((void**)&p_val, g_val_h);
    cudaGetSymbolAddress((void**)&p_attn,g_attn_h);
    cudaGetSymbolAddress((void**)&p_hn2, g_hn2_h);
    cudaGetSymbolAddress((void**)&p_mid, g_mid_h);
    cudaGetSymbolAddress((void**)&p_zhi, g_zhi);
    cudaGetSymbolAddress((void**)&p_zlo, g_zlo);
    cudaGetSymbolAddress((void**)&p_wv,  g_wv_h);
    cudaGetSymbolAddress((void**)&p_wca, g_wca_h);
    cudaGetSymbolAddress((void**)&p_wcn, g_wcn_h);
    cudaGetSymbolAddress((void**)&p_wo,  g_wo_h);
    cudaGetSymbolAddress((void**)&p_w1,  g_w1_h);
    cudaGetSymbolAddress((void**)&p_w2,  g_w2_h);
    cudaGetSymbolAddress((void**)&p_z,   g_z_h);

    constexpr int SM128 = ((3 * (128*40 + 32*136) * 2) > (128*132*4)) ? (3 * (128*40 + 32*136) * 2) : (128*132*4);
    constexpr int SM64  = ((3 * (64*40 + 32*72) * 2) > (64*68*4)) ? (3 * (64*40 + 32*72) * 2) : (64*68*4);
    cudaFuncSetAttribute(gemm_h<128,128,EPI_BIAS_F32>, cudaFuncAttributeMaxDynamicSharedMemorySize, SM128);
    cudaFuncSetAttribute(gemm_h<128,128,EPI_RES_F32 >, cudaFuncAttributeMaxDynamicSharedMemorySize, SM128);
    cudaFuncSetAttribute(gemm_h<128,128,EPI_GELU_H  >, cudaFuncAttributeMaxDynamicSharedMemorySize, SM128);
    cudaFuncSetAttribute(gemm_h<128,128,EPI_BIAS_H  >, cudaFuncAttributeMaxDynamicSharedMemorySize, SM128);
    cudaFuncSetAttribute(gemm_h< 64, 64,EPI_RES_F32 >, cudaFuncAttributeMaxDynamicSharedMemorySize, SM64);
    cudaFuncSetAttribute(attn_mma,                     cudaFuncAttributeMaxDynamicSharedMemorySize, AT_SMEM);

    auto cvt = [&](const float* src, __half* dst, int n) {
        int n4 = n / 4;
        f2h_kernel<<<(n4 + 255) / 256, 256>>>(src, dst, n4);
    };

    cvt(wv,  p_wv,  D_*D_);
    cvt(z,   p_z,   BS_*DC_);
    cvt(wca, p_wca, DC_*H_*HC_);
    ln1024<true><<<BS_, 256>>>(h, ln1g, ln1b, p_hn);
    // zh = z @ wca + bca  (fp32, for the Dekker split)
    gemm_h<128,128,EPI_BIAS_F32><<<dim3(2, BS_/128), 128, SM128>>>(p_z, p_wca, bca, nullptr, p_zh, BS_, 256, DC_);
    // value = fp16(hn @ wv + bv)
    gemm_h<128,128,EPI_BIAS_H><<<dim3(D_/128, BS_/128), 128, SM128>>>(p_hn, p_wv, bv, nullptr, p_val, BS_, D_, D_);
    cvt(wcn, p_wcn, D_*DC_);
    cvt(wo,  p_wo,  D_*D_);
    cvt(w1,  p_w1,  D_*MFF_);
    cvt(w2,  p_w2,  MFF_*D_);
    // Dekker split + norms
    score_prep<<<(BS_*H_ + 255) / 256, 256>>>(p_zh, p_zhi, p_zlo, p_zsq);
    // z_tmp = z + (hn @ wcn + bcn)
    gemm_h<64,64,EPI_RES_F32><<<dim3(1, BS_/64), 128, SM64>>>(p_hn, p_wcn, bcn, z, p_ztmp, BS_, DC_, D_);
    // fused flash attention: attn = fp16(softmax(-g*dist) @ V), P never hits HBM
    attn_mma<<<dim3(S_/128, BH_), 256, AT_SMEM>>>(p_zhi, p_zlo, p_zsq, gamma, p_val, p_attn);
    // h1 = h + (attn @ wo + bo)
    gemm_h<128,128,EPI_RES_F32><<<dim3(D_/128, BS_/128), 128, SM128>>>(p_attn, p_wo, bo, h, p_h1, BS_, D_, D_);
    // hn2 = fp16(LN2(h1))
    ln1024<true><<<BS_, 256>>>(p_h1, ln2g, ln2b, p_hn2);
    // mid = fp16(gelu(hn2 @ w1 + b1))
    gemm_h<128,128,EPI_GELU_H><<<dim3(MFF_/128, BS_/128), 128, SM128>>>(p_hn2, p_w1, b1, nullptr, p_mid, BS_, MFF_, D_);
    // out_h = h1 + (mid @ w2 + b2)
    gemm_h<128,128,EPI_RES_F32><<<dim3(D_/128, BS_/128), 128, SM128>>>(p_mid, p_w2, b2, p_h1, out_h, BS_, D_, MFF_);
    // out_z = LN_c(z_tmp)
    ln_small<<<BS_, 32>>>(p_ztmp, lncg, lncb, out_z, DC_);
}